// round 6
// baseline (speedup 1.0000x reference)
#include <cuda_runtime.h>
#include <math.h>

#define N_   256
#define FB_  256
#define D_   64
#define H_   4
#define DH_  128
#define HD_  512   // H*DH
#define BD_  128
#define HBD_ 512   // H*BD
#define AK_  100
#define L_   4
#define EPS_ 1e-5f

// ---------------- scratch (device globals; zero-init, no allocations) ----------------
__device__ float g_d[N_ * N_];
__device__ unsigned char g_act[N_ * N_];
__device__ int   g_pairCount;                  // reset by last-layer kernel for next replay
__device__ int   g_pairList[N_ * N_];
__device__ float g_diffs[L_ * H_ * N_ * N_];   // only active entries written/read
__device__ float g_cdiffs[L_ * H_];
__device__ float g_q[N_ * D_];
__device__ float g_k[N_ * D_];
__device__ float g_pred0[N_];
__device__ float g_pq[2][N_ * HD_];            // layer-parity double buffers
__device__ float g_pk[2][N_ * HD_];
__device__ float g_pkT[2][HD_ * N_];
__device__ float g_vals[2][H_][N_];

__device__ __forceinline__ float mishf(float x) {
    float sp = (x > 20.f) ? x : log1pf(expf(x));
    return x * tanhf(sp);
}

// ---------------- K0: embedding + pred0 + distances + layer-0 projections ----------------
__global__ void k_initdist(const float* __restrict__ X, const float* __restrict__ E,
                           const float* __restrict__ embW, const float* __restrict__ embB,
                           const float* __restrict__ boutW, const float* __restrict__ boutB,
                           const float* __restrict__ qpW, const float* __restrict__ qpB,
                           const float* __restrict__ kpW, const float* __restrict__ kpB,
                           float* __restrict__ out) {
    __shared__ float sx[FB_];
    __shared__ float se[AK_];
    __shared__ float red[256];
    __shared__ float sq[64];
    __shared__ float wred[8];
    int i = blockIdx.x, t = threadIdx.x;                  // 256 threads
    sx[t] = X[i * FB_ + t];
    if (t < AK_) se[t] = E[i * AK_ + t];
    if (t == 0) out[i] = 0.f;
    __syncthreads();
    // ---- distances ----
    float sqd = 0.f;
    const float* Ej = E + t * AK_;
#pragma unroll 4
    for (int a = 0; a < AK_; a++) { float d = se[a] - Ej[a]; sqd += d * d; }
    float dd = (sqd > 0.f) ? sqrtf(sqd) : 0.f;
    g_d[i * N_ + t] = dd;
    // d > 2 => every RBF term exp(< -127) == exactly 0.0f in fp32 (same as reference)
    bool act = (dd <= 2.0f);
    g_act[i * N_ + t] = act ? 1 : 0;
    if (act) {
        int p = atomicAdd(&g_pairCount, 1);
        g_pairList[p] = i * N_ + t;
    }
    // ---- embedding ----
    {
        int c = t & 63, part = t >> 6;
        float acc = 0.f;
        const float* wp = embW + (part * 64) * D_ + c;
#pragma unroll 16
        for (int f = 0; f < 64; f++) acc += sx[part * 64 + f] * wp[f * D_];
        red[t] = acc;
    }
    __syncthreads();
    if (t < D_) {
        float v = red[t] + red[t + 64] + red[t + 128] + red[t + 192] + embB[t];
        g_q[i * D_ + t] = v;
        g_k[i * D_ + t] = v;
        sq[t] = v;
    }
    // ---- initial prediction ----
    float pacc = sx[t] * boutW[t];
#pragma unroll
    for (int s = 16; s > 0; s >>= 1) pacc += __shfl_xor_sync(0xFFFFFFFFu, pacc, s);
    if ((t & 31) == 0) wred[t >> 5] = pacc;
    __syncthreads();
    if (t == 0) {
        float s = 0.f;
#pragma unroll
        for (int w = 0; w < 8; w++) s += wred[w];
        g_pred0[i] = s + boutB[0];
    }
    // ---- layer-0 projections: 2 q-cols + 2 k-cols per thread ----
    float aq0 = 0.f, aq1 = 0.f, ak0 = 0.f, ak1 = 0.f;
#pragma unroll 8
    for (int c = 0; c < D_; c++) {
        float s = sq[c];
        float2 wq = *(const float2*)(qpW + c * HD_ + 2 * t);
        float2 wk = *(const float2*)(kpW + c * HD_ + 2 * t);
        aq0 += s * wq.x; aq1 += s * wq.y;
        ak0 += s * wk.x; ak1 += s * wk.y;
    }
    int oc = 2 * t;
    aq0 += qpB[oc]; aq1 += qpB[oc + 1];
    ak0 += kpB[oc]; ak1 += kpB[oc + 1];
    g_pq[0][i * HD_ + oc] = aq0;  g_pq[0][i * HD_ + oc + 1] = aq1;
    g_pk[0][i * HD_ + oc] = ak0;  g_pk[0][i * HD_ + oc + 1] = ak1;
    g_pkT[0][oc * N_ + i] = ak0;  g_pkT[0][(oc + 1) * N_ + i] = ak1;
}

// ---------------- K1: bias pipeline. Virtual pair 0 = constant (beta=0) path ----------------
__global__ void k_active(const float* __restrict__ bpW, const float* __restrict__ bpB,
                         const float* __restrict__ bowW, const float* __restrict__ bowB) {
    __shared__ float beta[8][BD_];
    __shared__ float sb[8][HBD_];
    __shared__ int   svp[8];
    __shared__ float sd[8];
    int tid = threadIdx.x;                                // 512 threads
    int total = g_pairCount + 1;                          // +1 constant pseudo-pair
    int nChunks = (total + 7) >> 3;
    for (int ch = blockIdx.x; ch < nChunks; ch += gridDim.x) {
        int pbase = ch << 3;
        int np = total - pbase; if (np > 8) np = 8;
        if (tid < 8) {
            int vp = pbase + tid;
            if (tid < np) {
                if (vp == 0) { svp[tid] = -1; sd[tid] = 0.f; }          // constant path
                else { int pr = g_pairList[vp - 1]; svp[tid] = pr; sd[tid] = g_d[pr]; }
            } else { svp[tid] = -2; sd[tid] = 0.f; }
        }
        __syncthreads();
        for (int idx = tid; idx < 8 * BD_; idx += 512) {
            int p = idx >> 7, c = idx & 127;
            float ddv = sd[p] - (float)c * (1.0f / 127.0f);
            beta[p][c] = (p < np && svp[p] >= 0) ? expf(-127.0f * ddv * ddv) : 0.f;
        }
        __syncthreads();
        for (int l = 0; l < L_; l++) {
            const float* W = bpW + l * BD_ * HBD_;
            float acc[8];
#pragma unroll
            for (int p = 0; p < 8; p++) acc[p] = 0.f;
#pragma unroll 8
            for (int c = 0; c < BD_; c++) {
                float w = W[c * HBD_ + tid];
#pragma unroll
                for (int p = 0; p < 8; p++) acc[p] += beta[p][c] * w;
            }
            float bb = bpB[l * HBD_ + tid];
#pragma unroll
            for (int p = 0; p < 8; p++) sb[p][tid] = acc[p] + bb;
            __syncthreads();
            if (tid < 32) {
                int p = tid >> 2, h = tid & 3;
                if (p < np && svp[p] != -2) {
                    float s = 0.f;
#pragma unroll 8
                    for (int bd = 0; bd < BD_; bd++) { float v = sb[p][h * BD_ + bd]; s += v * v; }
                    float r = sqrtf(s);
                    if (svp[p] == -1) g_cdiffs[l * H_ + h] = r;
                    else              g_diffs[(l * H_ + h) * (N_ * N_) + svp[p]] = r;
                }
            }
            if (l < L_ - 1) {
                int c = tid & 127, g = tid >> 7;          // g in 0..3
                const float* W2 = bowW + l * HBD_ * BD_;
                float a0 = 0.f, a1 = 0.f;
#pragma unroll 8
                for (int o = 0; o < HBD_; o++) {
                    float w = W2[o * BD_ + c];
                    a0 += sb[g][o] * w;
                    a1 += sb[g + 4][o] * w;
                }
                float bb2 = bowB[l * BD_ + c];
                beta[g][c]     = mishf(a0 + bb2);
                beta[g + 4][c] = mishf(a1 + bb2);
            }
            __syncthreads();
        }
        __syncthreads();
    }
}

// ---------------- K2: attention (blocks 0-255) + update+next-proj (blocks 256-319) --------
__global__ void k_layer(const float* __restrict__ nt,
                        const float* __restrict__ qoW, const float* __restrict__ qoB,
                        const float* __restrict__ koW, const float* __restrict__ koB,
                        const float* __restrict__ qlnG, const float* __restrict__ qlnB,
                        const float* __restrict__ klnG, const float* __restrict__ klnB,
                        const float* __restrict__ qpW, const float* __restrict__ qpB,
                        const float* __restrict__ kpW, const float* __restrict__ kpB,
                        int l, int isLast, float* __restrict__ out) {
    __shared__ __align__(16) char smemRaw[34816];
    int tid = threadIdx.x;                                // 256 threads
    int buf = l & 1;
    if (blockIdx.x < 256) {
        // ======== attention: (head h, 4-row i tile) ========
        float4 (*pqs4)[32] = (float4(*)[32])smemRaw;              // 2 KB
        float  (*red)[256] = (float(*)[256])(smemRaw + 2048);     // 4 KB
        int h = blockIdx.x & 3, i0 = (blockIdx.x >> 2) * 4;
        if (isLast && blockIdx.x == 0 && tid == 0) g_pairCount = 0;   // prep next replay
        if (tid < 128)
            pqs4[tid >> 5][tid & 31] =
                ((const float4*)(g_pq[buf] + (i0 + (tid >> 5)) * HD_ + h * DH_))[tid & 31];
        __syncthreads();
        int j = tid;
        float a0 = 0.f, a1 = 0.f, a2 = 0.f, a3 = 0.f;
        const float* pkt = g_pkT[buf] + h * DH_ * N_;
#pragma unroll 4
        for (int d4 = 0; d4 < 32; d4++) {
            float4 q0 = pqs4[0][d4], q1 = pqs4[1][d4], q2 = pqs4[2][d4], q3 = pqs4[3][d4];
            const float* pb = pkt + (d4 * 4) * N_ + j;
            float k0 = pb[0], k1 = pb[N_], k2 = pb[2 * N_], k3 = pb[3 * N_];
            a0 += q0.x * k0 + q0.y * k1 + q0.z * k2 + q0.w * k3;
            a1 += q1.x * k0 + q1.y * k1 + q1.z * k2 + q1.w * k3;
            a2 += q2.x * k0 + q2.y * k1 + q2.z * k2 + q2.w * k3;
            a3 += q3.x * k0 + q3.y * k1 + q3.z * k2 + q3.w * k3;
        }
        const float scale = 0.0883883476483184f;          // 1/sqrt(128)
        float cd = g_cdiffs[l * H_ + h];
        const float* dptr = g_diffs + (l * H_ + h) * (N_ * N_);
        float av[4] = {a0, a1, a2, a3};
#pragma unroll
        for (int ii = 0; ii < 4; ii++) {
            int pr = (i0 + ii) * N_ + j;
            float dv = g_act[pr] ? dptr[pr] : cd;
            red[ii][j] = av[ii] * scale + dv;
        }
        __syncthreads();
        int w = tid >> 5, lane = tid & 31;
        if (w < 4) {                                      // warp w owns row i0+w
            float a[8];
#pragma unroll
            for (int k = 0; k < 8; k++) a[k] = red[w][k * 32 + lane];
            float mx = a[0];
#pragma unroll
            for (int k = 1; k < 8; k++) mx = fmaxf(mx, a[k]);
#pragma unroll
            for (int s = 16; s > 0; s >>= 1) mx = fmaxf(mx, __shfl_xor_sync(0xFFFFFFFFu, mx, s));
            float e[8], ssum = 0.f;
#pragma unroll
            for (int k = 0; k < 8; k++) { e[k] = expf(a[k] - mx); ssum += e[k]; }
#pragma unroll
            for (int s = 16; s > 0; s >>= 1) ssum += __shfl_xor_sync(0xFFFFFFFFu, ssum, s);
            int i = i0 + w;
            float predPrev;
            if (l == 0) predPrev = g_pred0[i];
            else {
                int pb2 = buf ^ 1;
                predPrev = 0.25f * (g_vals[pb2][0][i] + g_vals[pb2][1][i] +
                                    g_vals[pb2][2][i] + g_vals[pb2][3][i]);
            }
            float vs = 0.f;
#pragma unroll
            for (int k = 0; k < 8; k++) {
                int jj = k * 32 + lane;
                float v = (jj == i) ? predPrev : nt[jj];
                vs += e[k] * v;
            }
#pragma unroll
            for (int s = 16; s > 0; s >>= 1) vs += __shfl_xor_sync(0xFFFFFFFFu, vs, s);
            if (lane == 0) {
                float r = vs / ssum;
                if (isLast) atomicAdd(&out[i], 0.25f * r);
                else        g_vals[buf][h][i] = r;
            }
        }
    } else {
        // ======== update (8 rows) + projections for layer l+1 ========
        float (*sp)[HD_]  = (float(*)[HD_])smemRaw;               // 16 KB, permuted P
        float (*sqs)[64]  = (float(*)[64])(smemRaw + 16384);      // 2 KB, new q/k rows
        float (*spq)[HD_] = (float(*)[HD_])(smemRaw + 18432);     // 16 KB, proj out
        int ub = blockIdx.x - 256;
        bool isK = (ub >= 32);
        int r0 = (ub & 31) * 8;
        const float* P  = isK ? g_pk[buf] : g_pq[buf];
        const float* W  = (isK ? koW : qoW) + l * HD_ * D_;
        const float* Bi = (isK ? koB : qoB) + l * D_;
        const float* G  = (isK ? klnG : qlnG) + l * D_;
        const float* Bt = (isK ? klnB : qlnB) + l * D_;
        float* dst = isK ? g_k : g_q;
        // permuted fill: sp[r][m] = flat[m] = P[r, (m&3)*128 + (m>>2)]
        for (int idx = tid; idx < 8 * HD_; idx += 256) {
            int r = idx >> 9, s = idx & 511;
            int m = ((s & 127) << 2) | (s >> 7);
            sp[r][m] = P[(r0 + r) * HD_ + s];
        }
        __syncthreads();
        int rr = tid >> 5, cp = tid & 31;                 // row, col-pair
        int c0 = 2 * cp, c1 = c0 + 1;
        float acc0 = 0.f, acc1 = 0.f;
        const float4* sp4 = (const float4*)sp[rr];
#pragma unroll 4
        for (int m4 = 0; m4 < 128; m4++) {
            float4 pv = sp4[m4];
            const float* wb = W + (4 * m4) * D_ + c0;
            float2 w0 = *(const float2*)(wb);
            float2 w1 = *(const float2*)(wb + D_);
            float2 w2 = *(const float2*)(wb + 2 * D_);
            float2 w3 = *(const float2*)(wb + 3 * D_);
            acc0 += pv.x * w0.x + pv.y * w1.x + pv.z * w2.x + pv.w * w3.x;
            acc1 += pv.x * w0.y + pv.y * w1.y + pv.z * w2.y + pv.w * w3.y;
        }
        float y0 = dst[(r0 + rr) * D_ + c0] + mishf(acc0 + Bi[c0]);
        float y1 = dst[(r0 + rr) * D_ + c1] + mishf(acc1 + Bi[c1]);
        float s = y0 + y1, q2 = y0 * y0 + y1 * y1;
#pragma unroll
        for (int sh = 16; sh > 0; sh >>= 1) {
            s  += __shfl_xor_sync(0xFFFFFFFFu, s, sh);
            q2 += __shfl_xor_sync(0xFFFFFFFFu, q2, sh);
        }
        float mean = s * (1.0f / 64.0f);
        float var  = q2 * (1.0f / 64.0f) - mean * mean;
        float rstd = rsqrtf(var + EPS_);
        float o0 = (y0 - mean) * rstd * G[c0] + Bt[c0];
        float o1 = (y1 - mean) * rstd * G[c1] + Bt[c1];
        dst[(r0 + rr) * D_ + c0] = o0;
        dst[(r0 + rr) * D_ + c1] = o1;
        sqs[rr][c0] = o0;
        sqs[rr][c1] = o1;
        __syncthreads();
        // projections for layer l+1: 16 output cols per thread
        const float* Wq = (isK ? kpW : qpW) + (l + 1) * D_ * HD_;
        const float* Bq = (isK ? kpB : qpB) + (l + 1) * HD_;
        int ocg = cp;                                     // output group of 16
        float pacc[16];
#pragma unroll
        for (int u = 0; u < 16; u++) pacc[u] = 0.f;
#pragma unroll 2
        for (int c = 0; c < D_; c++) {
            float sv = sqs[rr][c];
            const float4* wp = (const float4*)(Wq + c * HD_ + ocg * 16);
            float4 w0 = wp[0], w1 = wp[1], w2 = wp[2], w3 = wp[3];
            pacc[0]  += sv * w0.x; pacc[1]  += sv * w0.y; pacc[2]  += sv * w0.z; pacc[3]  += sv * w0.w;
            pacc[4]  += sv * w1.x; pacc[5]  += sv * w1.y; pacc[6]  += sv * w1.z; pacc[7]  += sv * w1.w;
            pacc[8]  += sv * w2.x; pacc[9]  += sv * w2.y; pacc[10] += sv * w2.z; pacc[11] += sv * w2.w;
            pacc[12] += sv * w3.x; pacc[13] += sv * w3.y; pacc[14] += sv * w3.z; pacc[15] += sv * w3.w;
        }
#pragma unroll
        for (int u = 0; u < 16; u++)
            spq[rr][ocg * 16 + u] = pacc[u] + Bq[ocg * 16 + u];
        __syncthreads();
        int nbuf = buf ^ 1;
        float* dstP = isK ? g_pk[nbuf] : g_pq[nbuf];
        const float4* spq4 = (const float4*)spq;
        float4* dp4 = (float4*)(dstP + r0 * HD_);
        for (int idx = tid; idx < 8 * HD_ / 4; idx += 256) dp4[idx] = spq4[idx];
        if (isK) {
            float* pkTd = g_pkT[nbuf];
#pragma unroll
            for (int cs = 0; cs < 2; cs++) {
                int cc = 2 * tid + cs;
                float4 v0 = make_float4(spq[0][cc], spq[1][cc], spq[2][cc], spq[3][cc]);
                float4 v1 = make_float4(spq[4][cc], spq[5][cc], spq[6][cc], spq[7][cc]);
                *(float4*)(pkTd + cc * N_ + r0)     = v0;
                *(float4*)(pkTd + cc * N_ + r0 + 4) = v1;
            }
        }
    }
}

// ---------------- launch ----------------
extern "C" void kernel_launch(void* const* d_in, const int* in_sizes, int n_in,
                              void* d_out, int out_size) {
    const float* X     = (const float*)d_in[0];
    const float* E     = (const float*)d_in[1];
    const float* nt    = (const float*)d_in[2];
    const float* embW  = (const float*)d_in[3];
    const float* embB  = (const float*)d_in[4];
    const float* boutW = (const float*)d_in[5];
    const float* boutB = (const float*)d_in[6];
    const float* qpW   = (const float*)d_in[7];
    const float* qpB   = (const float*)d_in[8];
    const float* kpW   = (const float*)d_in[9];
    const float* kpB   = (const float*)d_in[10];
    const float* qoW   = (const float*)d_in[11];
    const float* qoB   = (const float*)d_in[12];
    const float* koW   = (const float*)d_in[13];
    const float* koB   = (const float*)d_in[14];
    const float* bpW   = (const float*)d_in[15];
    const float* bpB   = (const float*)d_in[16];
    const float* bowW  = (const float*)d_in[17];
    const float* bowB  = (const float*)d_in[18];
    const float* qlnG  = (const float*)d_in[19];
    const float* qlnB  = (const float*)d_in[20];
    const float* klnG  = (const float*)d_in[21];
    const float* klnB  = (const float*)d_in[22];
    float* out = (float*)d_out;

    k_initdist<<<N_, 256>>>(X, E, embW, embB, boutW, boutB, qpW, qpB, kpW, kpB, out);
    k_active<<<64, 512>>>(bpW, bpB, bowW, bowB);
    for (int l = 0; l < L_; l++) {
        int isLast = (l == L_ - 1);
        k_layer<<<isLast ? 256 : 320, 256>>>(nt, qoW, qoB, koW, koB,
                                             qlnG, qlnB, klnG, klnB,
                                             qpW, qpB, kpW, kpB, l, isLast, out);
    }
}

// round 7
// speedup vs baseline: 1.9125x; 1.9125x over previous
#include <cuda_runtime.h>
#include <math.h>

#define N_   256
#define FB_  256
#define D_   64
#define H_   4
#define DH_  128
#define HD_  512   // H*DH
#define BD_  128
#define HBD_ 512   // H*BD
#define AK_  100
#define L_   4
#define EPS_ 1e-5f

// ---------------- scratch (device globals; zero-init, no allocations) ----------------
__device__ float g_d[N_ * N_];
__device__ unsigned char g_act[N_ * N_];
__device__ int   g_pairCount;                  // reset by last-layer kernel for next replay
__device__ int   g_pairList[N_ * N_];
__device__ float g_diffs[L_ * H_ * N_ * N_];   // only active entries written/read
__device__ float g_cdiffs[L_ * H_];
__device__ float g_q[N_ * D_];
__device__ float g_k[N_ * D_];
__device__ float g_pred0[N_];
__device__ float g_pq[N_ * HD_];
__device__ float g_pk[N_ * HD_];
__device__ float g_pkTI[HD_ / 4 * N_ * 4];     // interleaved: [(dh>>2)*N + j]*4 + (dh&3)
__device__ float g_vals[2][H_][N_];

__device__ __forceinline__ float mishf(float x) {
    float sp = (x > 20.f) ? x : log1pf(expf(x));
    return x * tanhf(sp);
}

// ---------------- K0: embedding + initial predictions + distances + out zero ----------------
__global__ void k_initdist(const float* __restrict__ X, const float* __restrict__ E,
                           const float* __restrict__ embW, const float* __restrict__ embB,
                           const float* __restrict__ boutW, const float* __restrict__ boutB,
                           float* __restrict__ out) {
    __shared__ float sx[FB_];
    __shared__ float se[AK_];
    __shared__ float red[256];
    __shared__ float wred[8];
    int i = blockIdx.x, t = threadIdx.x;                  // 256 threads
    sx[t] = X[i * FB_ + t];
    if (t < AK_) se[t] = E[i * AK_ + t];
    if (t == 0) out[i] = 0.f;
    __syncthreads();
    // ---- distances ----
    float sqd = 0.f;
    const float* Ej = E + t * AK_;
#pragma unroll 4
    for (int a = 0; a < AK_; a++) { float d = se[a] - Ej[a]; sqd += d * d; }
    float dd = (sqd > 0.f) ? sqrtf(sqd) : 0.f;
    g_d[i * N_ + t] = dd;
    // d > 2 => every RBF term exp(< -127) == exactly 0.0f in fp32 (same as reference)
    bool act = (dd <= 2.0f);
    g_act[i * N_ + t] = act ? 1 : 0;
    if (act) {
        int p = atomicAdd(&g_pairCount, 1);
        g_pairList[p] = i * N_ + t;
    }
    // ---- embedding ----
    {
        int c = t & 63, part = t >> 6;
        float acc = 0.f;
        const float* wp = embW + (part * 64) * D_ + c;
#pragma unroll 16
        for (int f = 0; f < 64; f++) acc += sx[part * 64 + f] * wp[f * D_];
        red[t] = acc;
    }
    __syncthreads();
    if (t < D_) {
        float v = red[t] + red[t + 64] + red[t + 128] + red[t + 192] + embB[t];
        g_q[i * D_ + t] = v;
        g_k[i * D_ + t] = v;
    }
    // ---- initial prediction ----
    float pacc = sx[t] * boutW[t];
#pragma unroll
    for (int s = 16; s > 0; s >>= 1) pacc += __shfl_xor_sync(0xFFFFFFFFu, pacc, s);
    if ((t & 31) == 0) wred[t >> 5] = pacc;
    __syncthreads();
    if (t == 0) {
        float s = 0.f;
#pragma unroll
        for (int w = 0; w < 8; w++) s += wred[w];
        g_pred0[i] = s + boutB[0];
    }
}

// ---------------- K1: bias pipeline. Virtual pair 0 = constant (beta=0) path ----------------
__global__ void k_active(const float* __restrict__ bpW, const float* __restrict__ bpB,
                         const float* __restrict__ bowW, const float* __restrict__ bowB) {
    __shared__ float beta[8][BD_];
    __shared__ float sb[8][HBD_];
    __shared__ int   svp[8];
    __shared__ float sd[8];
    int tid = threadIdx.x;                                // 512 threads
    int total = g_pairCount + 1;                          // +1 constant pseudo-pair
    int nChunks = (total + 7) >> 3;
    for (int ch = blockIdx.x; ch < nChunks; ch += gridDim.x) {
        int pbase = ch << 3;
        int np = total - pbase; if (np > 8) np = 8;
        if (tid < 8) {
            int vp = pbase + tid;
            if (tid < np) {
                if (vp == 0) { svp[tid] = -1; sd[tid] = 0.f; }          // constant path
                else { int pr = g_pairList[vp - 1]; svp[tid] = pr; sd[tid] = g_d[pr]; }
            } else { svp[tid] = -2; sd[tid] = 0.f; }
        }
        __syncthreads();
        for (int idx = tid; idx < 8 * BD_; idx += 512) {
            int p = idx >> 7, c = idx & 127;
            float ddv = sd[p] - (float)c * (1.0f / 127.0f);
            beta[p][c] = (p < np && svp[p] >= 0) ? expf(-127.0f * ddv * ddv) : 0.f;
        }
        __syncthreads();
        for (int l = 0; l < L_; l++) {
            const float* W = bpW + l * BD_ * HBD_;
            float acc[8];
#pragma unroll
            for (int p = 0; p < 8; p++) acc[p] = 0.f;
#pragma unroll 8
            for (int c = 0; c < BD_; c++) {
                float w = W[c * HBD_ + tid];
#pragma unroll
                for (int p = 0; p < 8; p++) acc[p] += beta[p][c] * w;
            }
            float bb = bpB[l * HBD_ + tid];
#pragma unroll
            for (int p = 0; p < 8; p++) sb[p][tid] = acc[p] + bb;
            __syncthreads();
            if (tid < 32) {
                int p = tid >> 2, h = tid & 3;
                if (p < np && svp[p] != -2) {
                    float s = 0.f;
#pragma unroll 8
                    for (int bd = 0; bd < BD_; bd++) { float v = sb[p][h * BD_ + bd]; s += v * v; }
                    float r = sqrtf(s);
                    if (svp[p] == -1) g_cdiffs[l * H_ + h] = r;
                    else              g_diffs[(l * H_ + h) * (N_ * N_) + svp[p]] = r;
                }
            }
            if (l < L_ - 1) {
                int c = tid & 127, g = tid >> 7;          // g in 0..3
                const float* W2 = bowW + l * HBD_ * BD_;
                float a0 = 0.f, a1 = 0.f;
#pragma unroll 8
                for (int o = 0; o < HBD_; o++) {
                    float w = W2[o * BD_ + c];
                    a0 += sb[g][o] * w;
                    a1 += sb[g + 4][o] * w;
                }
                float bb2 = bowB[l * BD_ + c];
                beta[g][c]     = mishf(a0 + bb2);
                beta[g + 4][c] = mishf(a1 + bb2);
            }
            __syncthreads();
        }
        __syncthreads();
    }
}

// ---------------- K2: q/k projections (per layer), 128 blocks x 4 rows ----------------
__global__ void k_proj(const float* __restrict__ qpW, const float* __restrict__ qpB,
                       const float* __restrict__ kpW, const float* __restrict__ kpB, int l) {
    __shared__ float sx[4][D_];
    int b = blockIdx.x, tid = threadIdx.x;                // 512 threads
    bool isK = (b >= 64);
    int r0 = (b & 63) * 4;
    const float* src = isK ? g_k : g_q;
    const float* W  = (isK ? kpW : qpW) + l * D_ * HD_;
    const float* Bi = (isK ? kpB : qpB) + l * HD_;
    if (tid < 4 * D_) sx[tid >> 6][tid & 63] = src[(r0 + (tid >> 6)) * D_ + (tid & 63)];
    __syncthreads();
    float a0 = 0.f, a1 = 0.f, a2 = 0.f, a3 = 0.f;
#pragma unroll 16
    for (int c = 0; c < D_; c++) {
        float w = W[c * HD_ + tid];
        a0 += sx[0][c] * w;
        a1 += sx[1][c] * w;
        a2 += sx[2][c] * w;
        a3 += sx[3][c] * w;
    }
    float bb = Bi[tid];
    a0 += bb; a1 += bb; a2 += bb; a3 += bb;
    if (isK) {
        g_pk[(r0 + 0) * HD_ + tid] = a0;
        g_pk[(r0 + 1) * HD_ + tid] = a1;
        g_pk[(r0 + 2) * HD_ + tid] = a2;
        g_pk[(r0 + 3) * HD_ + tid] = a3;
        // interleaved transpose: [(dh>>2)*N + j]*4 + (dh&3)
        int base = ((tid >> 2) * N_) * 4 + (tid & 3);
        g_pkTI[base + (r0 + 0) * 4] = a0;
        g_pkTI[base + (r0 + 1) * 4] = a1;
        g_pkTI[base + (r0 + 2) * 4] = a2;
        g_pkTI[base + (r0 + 3) * 4] = a3;
    } else {
        g_pq[(r0 + 0) * HD_ + tid] = a0;
        g_pq[(r0 + 1) * HD_ + tid] = a1;
        g_pq[(r0 + 2) * HD_ + tid] = a2;
        g_pq[(r0 + 3) * HD_ + tid] = a3;
    }
}

// ---------------- K3: fused attention (blocks 0-255) + q/k update (blocks 256-383) --------
__global__ void k_layer(const float* __restrict__ nt,
                        const float* __restrict__ qoW, const float* __restrict__ qoB,
                        const float* __restrict__ koW, const float* __restrict__ koB,
                        const float* __restrict__ qlnG, const float* __restrict__ qlnB,
                        const float* __restrict__ klnG, const float* __restrict__ klnB,
                        int l, int isLast, float* __restrict__ out) {
    __shared__ __align__(16) char smemRaw[10240];
    int tid = threadIdx.x;                                // 256 threads
    if (blockIdx.x < 256) {
        // ======== attention: (head h, 4-row i tile) ========
        float4 (*pqs4)[32] = (float4(*)[32])smemRaw;              // 2 KB
        float  (*red)[256] = (float(*)[256])(smemRaw + 2048);     // 4 KB
        int h = blockIdx.x & 3, i0 = (blockIdx.x >> 2) * 4;
        if (isLast && blockIdx.x == 0 && tid == 0) g_pairCount = 0;   // prep next replay
        if (tid < 128)
            pqs4[tid >> 5][tid & 31] =
                ((const float4*)(g_pq + (i0 + (tid >> 5)) * HD_ + h * DH_))[tid & 31];
        __syncthreads();
        int j = tid;
        float a0 = 0.f, a1 = 0.f, a2 = 0.f, a3 = 0.f;
        const float4* pkt4 = (const float4*)(g_pkTI + (h * (DH_ / 4)) * N_ * 4) + j;
#pragma unroll 4
        for (int d4 = 0; d4 < 32; d4++) {
            float4 kv = pkt4[d4 * N_];
            float4 q0 = pqs4[0][d4], q1 = pqs4[1][d4], q2 = pqs4[2][d4], q3 = pqs4[3][d4];
            a0 += q0.x * kv.x + q0.y * kv.y + q0.z * kv.z + q0.w * kv.w;
            a1 += q1.x * kv.x + q1.y * kv.y + q1.z * kv.z + q1.w * kv.w;
            a2 += q2.x * kv.x + q2.y * kv.y + q2.z * kv.z + q2.w * kv.w;
            a3 += q3.x * kv.x + q3.y * kv.y + q3.z * kv.z + q3.w * kv.w;
        }
        const float scale = 0.0883883476483184f;          // 1/sqrt(128)
        float cd = g_cdiffs[l * H_ + h];
        const float* dptr = g_diffs + (l * H_ + h) * (N_ * N_);
        float av[4] = {a0, a1, a2, a3};
#pragma unroll
        for (int ii = 0; ii < 4; ii++) {
            int pr = (i0 + ii) * N_ + j;
            float dv = g_act[pr] ? dptr[pr] : cd;
            red[ii][j] = av[ii] * scale + dv;
        }
        __syncthreads();
        int w = tid >> 5, lane = tid & 31;
        if (w < 4) {                                      // warp w owns row i0+w
            float a[8];
#pragma unroll
            for (int k = 0; k < 8; k++) a[k] = red[w][k * 32 + lane];
            float mx = a[0];
#pragma unroll
            for (int k = 1; k < 8; k++) mx = fmaxf(mx, a[k]);
#pragma unroll
            for (int s = 16; s > 0; s >>= 1) mx = fmaxf(mx, __shfl_xor_sync(0xFFFFFFFFu, mx, s));
            float e[8], ssum = 0.f;
#pragma unroll
            for (int k = 0; k < 8; k++) { e[k] = expf(a[k] - mx); ssum += e[k]; }
#pragma unroll
            for (int s = 16; s > 0; s >>= 1) ssum += __shfl_xor_sync(0xFFFFFFFFu, ssum, s);
            int i = i0 + w;
            float predPrev;
            if (l == 0) predPrev = g_pred0[i];
            else {
                int pb2 = (l & 1) ^ 1;
                predPrev = 0.25f * (g_vals[pb2][0][i] + g_vals[pb2][1][i] +
                                    g_vals[pb2][2][i] + g_vals[pb2][3][i]);
            }
            float vs = 0.f;
#pragma unroll
            for (int k = 0; k < 8; k++) {
                int jj = k * 32 + lane;
                float v = (jj == i) ? predPrev : nt[jj];
                vs += e[k] * v;
            }
#pragma unroll
            for (int s = 16; s > 0; s >>= 1) vs += __shfl_xor_sync(0xFFFFFFFFu, vs, s);
            if (lane == 0) {
                float r = vs / ssum;
                if (isLast) atomicAdd(&out[i], 0.25f * r);
                else        g_vals[l & 1][h][i] = r;
            }
        }
    } else {
        // ======== residual + mish + LayerNorm for q/k, 4 rows per block ========
        float (*sp)[HD_] = (float(*)[HD_])smemRaw;                // 8 KB (flat-permuted)
        float (*srs)[64] = (float(*)[64])(smemRaw + 8192);        // 1 KB
        float (*srq)[64] = (float(*)[64])(smemRaw + 9216);        // 1 KB
        int ub = blockIdx.x - 256;
        bool isK = (ub >= 64);
        int r0 = (ub & 63) * 4;
        const float* P  = isK ? g_pk : g_pq;
        const float* W  = (isK ? koW : qoW) + l * HD_ * D_;
        const float* Bi = (isK ? koB : qoB) + l * D_;
        const float* G  = (isK ? klnG : qlnG) + l * D_;
        const float* Bt = (isK ? klnB : qlnB) + l * D_;
        float* dst = isK ? g_k : g_q;
        // permuted fill: sp[r][m] = flat[m] = P[r, (m&3)*128 + (m>>2)]
        for (int idx = tid; idx < 4 * HD_; idx += 256) {
            int r = idx >> 9, s = idx & 511;
            int m = ((s & 127) << 2) | (s >> 7);
            sp[r][m] = P[(r0 + r) * HD_ + s];
        }
        __syncthreads();
        int r = tid >> 6, c = tid & 63;
        float acc = 0.f;
        const float4* sp4 = (const float4*)sp[r];
        const float* wc = W + c;
#pragma unroll 4
        for (int m4 = 0; m4 < 128; m4++) {
            float4 pv = sp4[m4];
            const float* wb = wc + (4 * m4) * D_;
            acc += pv.x * wb[0] + pv.y * wb[D_] + pv.z * wb[2 * D_] + pv.w * wb[3 * D_];
        }
        float y = dst[(r0 + r) * D_ + c] + mishf(acc + Bi[c]);
        srs[r][c] = y;
        srq[r][c] = y * y;
        __syncthreads();
        for (int s = 32; s > 0; s >>= 1) {
            if (c < s) { srs[r][c] += srs[r][c + s]; srq[r][c] += srq[r][c + s]; }
            __syncthreads();
        }
        float mean = srs[r][0] * (1.0f / 64.0f);
        float var  = srq[r][0] * (1.0f / 64.0f) - mean * mean;
        float o    = (y - mean) * rsqrtf(var + EPS_) * G[c] + Bt[c];
        dst[(r0 + r) * D_ + c] = o;
    }
}

// ---------------- launch ----------------
extern "C" void kernel_launch(void* const* d_in, const int* in_sizes, int n_in,
                              void* d_out, int out_size) {
    const float* X     = (const float*)d_in[0];
    const float* E     = (const float*)d_in[1];
    const float* nt    = (const float*)d_in[2];
    const float* embW  = (const float*)d_in[3];
    const float* embB  = (const float*)d_in[4];
    const float* boutW = (const float*)d_in[5];
    const float* boutB = (const float*)d_in[6];
    const float* qpW   = (const float*)d_in[7];
    const float* qpB   = (const float*)d_in[8];
    const float* kpW   = (const float*)d_in[9];
    const float* kpB   = (const float*)d_in[10];
    const float* qoW   = (const float*)d_in[11];
    const float* qoB   = (const float*)d_in[12];
    const float* koW   = (const float*)d_in[13];
    const float* koB   = (const float*)d_in[14];
    const float* bpW   = (const float*)d_in[15];
    const float* bpB   = (const float*)d_in[16];
    const float* bowW  = (const float*)d_in[17];
    const float* bowB  = (const float*)d_in[18];
    const float* qlnG  = (const float*)d_in[19];
    const float* qlnB  = (const float*)d_in[20];
    const float* klnG  = (const float*)d_in[21];
    const float* klnB  = (const float*)d_in[22];
    float* out = (float*)d_out;

    k_initdist<<<N_, 256>>>(X, E, embW, embB, boutW, boutB, out);
    k_active<<<64, 512>>>(bpW, bpB, bowW, bowB);
    for (int l = 0; l < L_; l++) {
        int isLast = (l == L_ - 1);
        k_proj<<<128, 512>>>(qpW, qpB, kpW, kpB, l);
        k_layer<<<isLast ? 256 : 384, 256>>>(nt, qoW, qoB, koW, koB,
                                             qlnG, qlnB, klnG, klnB, l, isLast, out);
    }
}

// round 8
// speedup vs baseline: 2.2304x; 1.1662x over previous
#include <cuda_runtime.h>
#include <math.h>

#define N_   256
#define FB_  256
#define D_   64
#define H_   4
#define DH_  128
#define HD_  512   // H*DH
#define BD_  128
#define HBD_ 512   // H*BD
#define AK_  100
#define L_   4
#define EPS_ 1e-5f

// ---------------- scratch (device globals; zero-init, no allocations) ----------------
__device__ float g_d[N_ * N_];
__device__ unsigned char g_act[N_ * N_];
__device__ int   g_pairCount;                  // reset by last-layer kernel for next replay
__device__ int   g_pairList[N_ * N_];
__device__ float g_diffs[L_ * H_ * N_ * N_];   // only active entries written/read
__device__ float g_cdiffs[L_ * H_];
__device__ float g_q[N_ * D_];
__device__ float g_k[N_ * D_];
__device__ float g_pred0[N_];
__device__ float g_pq[N_ * HD_];
__device__ float g_pk[N_ * HD_];
__device__ float g_pkTI[HD_ / 4 * N_ * 4];     // interleaved: [((h*32+d4)*N + j)*4 + (dh&3)]
__device__ float g_vals[2][H_][N_];

__device__ __forceinline__ float mishf(float x) {
    float sp = (x > 20.f) ? x : log1pf(expf(x));
    return x * tanhf(sp);
}

// ---------------- K0: embedding + initial predictions + distances + out zero ----------------
__global__ void k_initdist(const float* __restrict__ X, const float* __restrict__ E,
                           const float* __restrict__ embW, const float* __restrict__ embB,
                           const float* __restrict__ boutW, const float* __restrict__ boutB,
                           float* __restrict__ out) {
    __shared__ float sx[FB_];
    __shared__ float se[AK_];
    __shared__ float red[256];
    __shared__ float wred[8];
    int i = blockIdx.x, t = threadIdx.x;                  // 256 threads
    sx[t] = X[i * FB_ + t];
    if (t < AK_) se[t] = E[i * AK_ + t];
    if (t == 0) out[i] = 0.f;
    __syncthreads();
    // ---- distances ----
    float sqd = 0.f;
    const float* Ej = E + t * AK_;
#pragma unroll 4
    for (int a = 0; a < AK_; a++) { float d = se[a] - Ej[a]; sqd += d * d; }
    float dd = (sqd > 0.f) ? sqrtf(sqd) : 0.f;
    g_d[i * N_ + t] = dd;
    // d > 2 => every RBF term exp(< -127) == exactly 0.0f in fp32 (same as reference)
    bool act = (dd <= 2.0f);
    g_act[i * N_ + t] = act ? 1 : 0;
    if (act) {
        int p = atomicAdd(&g_pairCount, 1);
        g_pairList[p] = i * N_ + t;
    }
    // ---- embedding ----
    {
        int c = t & 63, part = t >> 6;
        float acc = 0.f;
        const float* wp = embW + (part * 64) * D_ + c;
#pragma unroll 16
        for (int f = 0; f < 64; f++) acc += sx[part * 64 + f] * wp[f * D_];
        red[t] = acc;
    }
    __syncthreads();
    if (t < D_) {
        float v = red[t] + red[t + 64] + red[t + 128] + red[t + 192] + embB[t];
        g_q[i * D_ + t] = v;
        g_k[i * D_ + t] = v;
    }
    // ---- initial prediction ----
    float pacc = sx[t] * boutW[t];
#pragma unroll
    for (int s = 16; s > 0; s >>= 1) pacc += __shfl_xor_sync(0xFFFFFFFFu, pacc, s);
    if ((t & 31) == 0) wred[t >> 5] = pacc;
    __syncthreads();
    if (t == 0) {
        float s = 0.f;
#pragma unroll
        for (int w = 0; w < 8; w++) s += wred[w];
        g_pred0[i] = s + boutB[0];
    }
}

// ---------------- K1: bias pipeline, 4 pairs/chunk. Virtual pair 0 = constant path --------
__global__ void k_active(const float* __restrict__ bpW, const float* __restrict__ bpB,
                         const float* __restrict__ bowW, const float* __restrict__ bowB) {
    __shared__ float beta[4][BD_];
    __shared__ float sb[4][HBD_];
    __shared__ int   svp[4];
    __shared__ float sd[4];
    int tid = threadIdx.x;                                // 512 threads
    int total = g_pairCount + 1;                          // +1 constant pseudo-pair
    int nChunks = (total + 3) >> 2;
    for (int ch = blockIdx.x; ch < nChunks; ch += gridDim.x) {
        int pbase = ch << 2;
        int np = total - pbase; if (np > 4) np = 4;
        if (tid < 4) {
            int vp = pbase + tid;
            if (tid < np) {
                if (vp == 0) { svp[tid] = -1; sd[tid] = 0.f; }          // constant path
                else { int pr = g_pairList[vp - 1]; svp[tid] = pr; sd[tid] = g_d[pr]; }
            } else { svp[tid] = -2; sd[tid] = 0.f; }
        }
        __syncthreads();
        if (tid < 4 * BD_) {
            int p = tid >> 7, c = tid & 127;
            float ddv = sd[p] - (float)c * (1.0f / 127.0f);
            beta[p][c] = (p < np && svp[p] >= 0) ? expf(-127.0f * ddv * ddv) : 0.f;
        }
        __syncthreads();
        for (int l = 0; l < L_; l++) {
            const float* W = bpW + l * BD_ * HBD_;
            float acc0 = 0.f, acc1 = 0.f, acc2 = 0.f, acc3 = 0.f;
#pragma unroll 8
            for (int c = 0; c < BD_; c++) {
                float w = W[c * HBD_ + tid];
                acc0 += beta[0][c] * w;
                acc1 += beta[1][c] * w;
                acc2 += beta[2][c] * w;
                acc3 += beta[3][c] * w;
            }
            float bb = bpB[l * HBD_ + tid];
            sb[0][tid] = acc0 + bb;
            sb[1][tid] = acc1 + bb;
            sb[2][tid] = acc2 + bb;
            sb[3][tid] = acc3 + bb;
            __syncthreads();
            if (tid < 16) {
                int p = tid >> 2, h = tid & 3;
                if (p < np && svp[p] != -2) {
                    float s = 0.f;
#pragma unroll 8
                    for (int bd = 0; bd < BD_; bd++) { float v = sb[p][h * BD_ + bd]; s += v * v; }
                    float r = sqrtf(s);
                    if (svp[p] == -1) g_cdiffs[l * H_ + h] = r;
                    else              g_diffs[(l * H_ + h) * (N_ * N_) + svp[p]] = r;
                }
            }
            if (l < L_ - 1) {
                int c = tid & 127, g = tid >> 7;          // g in 0..3: one pair per group
                const float* W2 = bowW + l * HBD_ * BD_;
                float a0 = 0.f;
#pragma unroll 8
                for (int o = 0; o < HBD_; o++) a0 += sb[g][o] * W2[o * BD_ + c];
                float bb2 = bowB[l * BD_ + c];
                __syncthreads();
                beta[g][c] = mishf(a0 + bb2);
            } else {
                __syncthreads();
            }
            __syncthreads();
        }
    }
}

// ---------------- K2: q/k projections (per layer), 128 blocks x 4 rows ----------------
__global__ void k_proj(const float* __restrict__ qpW, const float* __restrict__ qpB,
                       const float* __restrict__ kpW, const float* __restrict__ kpB, int l) {
    __shared__ float sx[4][D_];
    int b = blockIdx.x, tid = threadIdx.x;                // 512 threads
    bool isK = (b >= 64);
    int r0 = (b & 63) * 4;
    const float* src = isK ? g_k : g_q;
    const float* W  = (isK ? kpW : qpW) + l * D_ * HD_;
    const float* Bi = (isK ? kpB : qpB) + l * HD_;
    if (tid < 4 * D_) sx[tid >> 6][tid & 63] = src[(r0 + (tid >> 6)) * D_ + (tid & 63)];
    __syncthreads();
    float a0 = 0.f, a1 = 0.f, a2 = 0.f, a3 = 0.f;
#pragma unroll 16
    for (int c = 0; c < D_; c++) {
        float w = W[c * HD_ + tid];
        a0 += sx[0][c] * w;
        a1 += sx[1][c] * w;
        a2 += sx[2][c] * w;
        a3 += sx[3][c] * w;
    }
    float bb = Bi[tid];
    a0 += bb; a1 += bb; a2 += bb; a3 += bb;
    if (isK) {
        g_pk[(r0 + 0) * HD_ + tid] = a0;
        g_pk[(r0 + 1) * HD_ + tid] = a1;
        g_pk[(r0 + 2) * HD_ + tid] = a2;
        g_pk[(r0 + 3) * HD_ + tid] = a3;
        // interleaved transpose: [(dh>>2)*N + j]*4 + (dh&3)
        int base = ((tid >> 2) * N_) * 4 + (tid & 3);
        g_pkTI[base + (r0 + 0) * 4] = a0;
        g_pkTI[base + (r0 + 1) * 4] = a1;
        g_pkTI[base + (r0 + 2) * 4] = a2;
        g_pkTI[base + (r0 + 3) * 4] = a3;
    } else {
        g_pq[(r0 + 0) * HD_ + tid] = a0;
        g_pq[(r0 + 1) * HD_ + tid] = a1;
        g_pq[(r0 + 2) * HD_ + tid] = a2;
        g_pq[(r0 + 3) * HD_ + tid] = a3;
    }
}

// ---------------- K3: fused attention (blocks 0-127, 8-row tiles) + update (128-255) ------
__global__ void k_layer(const float* __restrict__ nt,
                        const float* __restrict__ qoW, const float* __restrict__ qoB,
                        const float* __restrict__ koW, const float* __restrict__ koB,
                        const float* __restrict__ qlnG, const float* __restrict__ qlnB,
                        const float* __restrict__ klnG, const float* __restrict__ klnB,
                        int l, int isLast, float* __restrict__ out) {
    __shared__ __align__(16) char smemRaw[12288];
    int tid = threadIdx.x;                                // 256 threads
    if (blockIdx.x < 128) {
        // ======== attention: (head h, 8-row i tile), interleaved K loads ========
        float4 (*pqs4)[32] = (float4(*)[32])smemRaw;              // 4 KB
        float  (*red)[256] = (float(*)[256])(smemRaw + 4096);     // 8 KB
        int h = blockIdx.x & 3, i0 = (blockIdx.x >> 2) * 8;
        if (isLast && blockIdx.x == 0 && tid == 0) g_pairCount = 0;   // prep next replay
        pqs4[tid >> 5][tid & 31] =
            ((const float4*)(g_pq + (i0 + (tid >> 5)) * HD_ + h * DH_))[tid & 31];
        __syncthreads();
        int j = tid;
        float acc[8];
#pragma unroll
        for (int ii = 0; ii < 8; ii++) acc[ii] = 0.f;
        const float4* pkt4 = (const float4*)(g_pkTI + (h * (DH_ / 4)) * N_ * 4) + j;
#pragma unroll 4
        for (int d4 = 0; d4 < 32; d4++) {
            float4 kv = pkt4[d4 * N_];
#pragma unroll
            for (int ii = 0; ii < 8; ii++) {
                float4 q = pqs4[ii][d4];
                acc[ii] += q.x * kv.x + q.y * kv.y + q.z * kv.z + q.w * kv.w;
            }
        }
        const float scale = 0.0883883476483184f;          // 1/sqrt(128)
        float cd = g_cdiffs[l * H_ + h];
        const float* dptr = g_diffs + (l * H_ + h) * (N_ * N_);
#pragma unroll
        for (int ii = 0; ii < 8; ii++) {
            int pr = (i0 + ii) * N_ + j;
            float dv = g_act[pr] ? dptr[pr] : cd;
            red[ii][j] = acc[ii] * scale + dv;
        }
        __syncthreads();
        // warp w owns row i0+w
        int w = tid >> 5, lane = tid & 31;
        float a[8];
#pragma unroll
        for (int k = 0; k < 8; k++) a[k] = red[w][k * 32 + lane];
        float mx = a[0];
#pragma unroll
        for (int k = 1; k < 8; k++) mx = fmaxf(mx, a[k]);
#pragma unroll
        for (int s = 16; s > 0; s >>= 1) mx = fmaxf(mx, __shfl_xor_sync(0xFFFFFFFFu, mx, s));
        float e[8], ssum = 0.f;
#pragma unroll
        for (int k = 0; k < 8; k++) { e[k] = expf(a[k] - mx); ssum += e[k]; }
#pragma unroll
        for (int s = 16; s > 0; s >>= 1) ssum += __shfl_xor_sync(0xFFFFFFFFu, ssum, s);
        int i = i0 + w;
        float predPrev;
        if (l == 0) predPrev = g_pred0[i];
        else {
            int pb2 = (l & 1) ^ 1;
            predPrev = 0.25f * (g_vals[pb2][0][i] + g_vals[pb2][1][i] +
                                g_vals[pb2][2][i] + g_vals[pb2][3][i]);
        }
        float vs = 0.f;
#pragma unroll
        for (int k = 0; k < 8; k++) {
            int jj = k * 32 + lane;
            float v = (jj == i) ? predPrev : nt[jj];
            vs += e[k] * v;
        }
#pragma unroll
        for (int s = 16; s > 0; s >>= 1) vs += __shfl_xor_sync(0xFFFFFFFFu, vs, s);
        if (lane == 0) {
            float r = vs / ssum;
            if (isLast) atomicAdd(&out[i], 0.25f * r);
            else        g_vals[l & 1][h][i] = r;
        }
    } else {
        // ======== residual + mish + LayerNorm for q/k, 4 rows per block ========
        float (*sp)[HD_] = (float(*)[HD_])smemRaw;                // 8 KB (flat-permuted)
        float (*srs)[64] = (float(*)[64])(smemRaw + 8192);        // 1 KB
        float (*srq)[64] = (float(*)[64])(smemRaw + 9216);        // 1 KB
        int ub = blockIdx.x - 128;
        bool isK = (ub >= 64);
        int r0 = (ub & 63) * 4;
        const float* P  = isK ? g_pk : g_pq;
        const float* W  = (isK ? koW : qoW) + l * HD_ * D_;
        const float* Bi = (isK ? koB : qoB) + l * D_;
        const float* G  = (isK ? klnG : qlnG) + l * D_;
        const float* Bt = (isK ? klnB : qlnB) + l * D_;
        float* dst = isK ? g_k : g_q;
        // permuted fill: sp[r][m] = flat[m] = P[r, (m&3)*128 + (m>>2)]
        for (int idx = tid; idx < 4 * HD_; idx += 256) {
            int r = idx >> 9, s = idx & 511;
            int m = ((s & 127) << 2) | (s >> 7);
            sp[r][m] = P[(r0 + r) * HD_ + s];
        }
        __syncthreads();
        int r = tid >> 6, c = tid & 63;
        float acc = 0.f;
        const float4* sp4 = (const float4*)sp[r];
        const float* wc = W + c;
#pragma unroll 4
        for (int m4 = 0; m4 < 128; m4++) {
            float4 pv = sp4[m4];
            const float* wb = wc + (4 * m4) * D_;
            acc += pv.x * wb[0] + pv.y * wb[D_] + pv.z * wb[2 * D_] + pv.w * wb[3 * D_];
        }
        float y = dst[(r0 + r) * D_ + c] + mishf(acc + Bi[c]);
        srs[r][c] = y;
        srq[r][c] = y * y;
        __syncthreads();
        for (int s = 32; s > 0; s >>= 1) {
            if (c < s) { srs[r][c] += srs[r][c + s]; srq[r][c] += srq[r][c + s]; }
            __syncthreads();
        }
        float mean = srs[r][0] * (1.0f / 64.0f);
        float var  = srq[r][0] * (1.0f / 64.0f) - mean * mean;
        float o    = (y - mean) * rsqrtf(var + EPS_) * G[c] + Bt[c];
        dst[(r0 + r) * D_ + c] = o;
    }
}

// ---------------- launch ----------------
extern "C" void kernel_launch(void* const* d_in, const int* in_sizes, int n_in,
                              void* d_out, int out_size) {
    const float* X     = (const float*)d_in[0];
    const float* E     = (const float*)d_in[1];
    const float* nt    = (const float*)d_in[2];
    const float* embW  = (const float*)d_in[3];
    const float* embB  = (const float*)d_in[4];
    const float* boutW = (const float*)d_in[5];
    const float* boutB = (const float*)d_in[6];
    const float* qpW   = (const float*)d_in[7];
    const float* qpB   = (const float*)d_in[8];
    const float* kpW   = (const float*)d_in[9];
    const float* kpB   = (const float*)d_in[10];
    const float* qoW   = (const float*)d_in[11];
    const float* qoB   = (const float*)d_in[12];
    const float* koW   = (const float*)d_in[13];
    const float* koB   = (const float*)d_in[14];
    const float* bpW   = (const float*)d_in[15];
    const float* bpB   = (const float*)d_in[16];
    const float* bowW  = (const float*)d_in[17];
    const float* bowB  = (const float*)d_in[18];
    const float* qlnG  = (const float*)d_in[19];
    const float* qlnB  = (const float*)d_in[20];
    const float* klnG  = (const float*)d_in[21];
    const float* klnB  = (const float*)d_in[22];
    float* out = (float*)d_out;

    k_initdist<<<N_, 256>>>(X, E, embW, embB, boutW, boutB, out);
    k_active<<<96, 512>>>(bpW, bpB, bowW, bowB);
    for (int l = 0; l < L_; l++) {
        int isLast = (l == L_ - 1);
        k_proj<<<128, 512>>>(qpW, qpB, kpW, kpB, l);
        k_layer<<<isLast ? 128 : 256, 256>>>(nt, qoW, qoB, koW, koB,
                                             qlnG, qlnB, klnG, klnB, l, isLast, out);
    }
}

// round 9
// speedup vs baseline: 2.2913x; 1.0273x over previous
#include <cuda_runtime.h>
#include <math.h>

#define N_   256
#define FB_  256
#define D_   64
#define H_   4
#define DH_  128
#define HD_  512   // H*DH
#define BD_  128
#define HBD_ 512   // H*BD
#define AK_  100
#define L_   4
#define EPS_ 1e-5f

// ---------------- scratch (device globals; zero-init, no allocations) ----------------
__device__ float g_d[N_ * N_];
__device__ unsigned char g_act[N_ * N_];
__device__ int   g_pairCount;                  // reset by last-layer kernel for next replay
__device__ int   g_pairList[N_ * N_];
__device__ float g_diffs[L_ * H_ * N_ * N_];   // only active entries written/read
__device__ float g_cdiffs[L_ * H_];
__device__ float g_q[N_ * D_];
__device__ float g_k[N_ * D_];
__device__ float g_pred0[N_];
__device__ float g_pq[N_ * HD_];
__device__ float g_pk[N_ * HD_];
__device__ float g_pkTI[HD_ / 4 * N_ * 4];     // interleaved: [((h*32+d4)*N + j)*4 + (dh&3)]
__device__ float g_vals[2][H_][N_];

__device__ __forceinline__ float mishf(float x) {
    float sp = (x > 20.f) ? x : log1pf(expf(x));
    return x * tanhf(sp);
}

// ---------------- K0: embedding + initial predictions + distances + out zero ----------------
__global__ void k_initdist(const float* __restrict__ X, const float* __restrict__ E,
                           const float* __restrict__ embW, const float* __restrict__ embB,
                           const float* __restrict__ boutW, const float* __restrict__ boutB,
                           float* __restrict__ out) {
    __shared__ float sx[FB_];
    __shared__ float se[AK_];
    __shared__ float red[256];
    __shared__ float wred[8];
    int i = blockIdx.x, t = threadIdx.x;                  // 256 threads
    sx[t] = X[i * FB_ + t];
    if (t < AK_) se[t] = E[i * AK_ + t];
    if (t == 0) out[i] = 0.f;
    __syncthreads();
    // ---- distances ----
    float sqd = 0.f;
    const float* Ej = E + t * AK_;
#pragma unroll 4
    for (int a = 0; a < AK_; a++) { float d = se[a] - Ej[a]; sqd += d * d; }
    float dd = (sqd > 0.f) ? sqrtf(sqd) : 0.f;
    g_d[i * N_ + t] = dd;
    // d > 2 => every RBF term exp(< -127) == exactly 0.0f in fp32 (same as reference)
    bool act = (dd <= 2.0f);
    g_act[i * N_ + t] = act ? 1 : 0;
    if (act) {
        int p = atomicAdd(&g_pairCount, 1);
        g_pairList[p] = i * N_ + t;
    }
    // ---- embedding ----
    {
        int c = t & 63, part = t >> 6;
        float acc = 0.f;
        const float* wp = embW + (part * 64) * D_ + c;
#pragma unroll 16
        for (int f = 0; f < 64; f++) acc += sx[part * 64 + f] * wp[f * D_];
        red[t] = acc;
    }
    __syncthreads();
    if (t < D_) {
        float v = red[t] + red[t + 64] + red[t + 128] + red[t + 192] + embB[t];
        g_q[i * D_ + t] = v;
        g_k[i * D_ + t] = v;
    }
    // ---- initial prediction ----
    float pacc = sx[t] * boutW[t];
#pragma unroll
    for (int s = 16; s > 0; s >>= 1) pacc += __shfl_xor_sync(0xFFFFFFFFu, pacc, s);
    if ((t & 31) == 0) wred[t >> 5] = pacc;
    __syncthreads();
    if (t == 0) {
        float s = 0.f;
#pragma unroll
        for (int w = 0; w < 8; w++) s += wred[w];
        g_pred0[i] = s + boutB[0];
    }
}

// ---------------- K1: bias pipeline, 4 pairs/chunk. Virtual pair 0 = constant path --------
__global__ void k_active(const float* __restrict__ bpW, const float* __restrict__ bpB,
                         const float* __restrict__ bowW, const float* __restrict__ bowB) {
    __shared__ float beta[4][BD_];
    __shared__ float sb[4][HBD_];
    __shared__ int   svp[4];
    __shared__ float sd[4];
    int tid = threadIdx.x;                                // 512 threads
    int total = g_pairCount + 1;                          // +1 constant pseudo-pair
    int nChunks = (total + 3) >> 2;
    for (int ch = blockIdx.x; ch < nChunks; ch += gridDim.x) {
        int pbase = ch << 2;
        int np = total - pbase; if (np > 4) np = 4;
        if (tid < 4) {
            int vp = pbase + tid;
            if (tid < np) {
                if (vp == 0) { svp[tid] = -1; sd[tid] = 0.f; }          // constant path
                else { int pr = g_pairList[vp - 1]; svp[tid] = pr; sd[tid] = g_d[pr]; }
            } else { svp[tid] = -2; sd[tid] = 0.f; }
        }
        __syncthreads();
        if (tid < 4 * BD_) {
            int p = tid >> 7, c = tid & 127;
            float ddv = sd[p] - (float)c * (1.0f / 127.0f);
            beta[p][c] = (p < np && svp[p] >= 0) ? expf(-127.0f * ddv * ddv) : 0.f;
        }
        __syncthreads();
        for (int l = 0; l < L_; l++) {
            const float* W = bpW + l * BD_ * HBD_;
            float acc0 = 0.f, acc1 = 0.f, acc2 = 0.f, acc3 = 0.f;
#pragma unroll 8
            for (int c = 0; c < BD_; c++) {
                float w = W[c * HBD_ + tid];
                acc0 += beta[0][c] * w;
                acc1 += beta[1][c] * w;
                acc2 += beta[2][c] * w;
                acc3 += beta[3][c] * w;
            }
            float bb = bpB[l * HBD_ + tid];
            sb[0][tid] = acc0 + bb;
            sb[1][tid] = acc1 + bb;
            sb[2][tid] = acc2 + bb;
            sb[3][tid] = acc3 + bb;
            __syncthreads();
            if (tid < 16) {
                int p = tid >> 2, h = tid & 3;
                if (p < np && svp[p] != -2) {
                    float s = 0.f;
#pragma unroll 8
                    for (int bd = 0; bd < BD_; bd++) { float v = sb[p][h * BD_ + bd]; s += v * v; }
                    float r = sqrtf(s);
                    if (svp[p] == -1) g_cdiffs[l * H_ + h] = r;
                    else              g_diffs[(l * H_ + h) * (N_ * N_) + svp[p]] = r;
                }
            }
            if (l < L_ - 1) {
                int c = tid & 127, g = tid >> 7;          // g in 0..3: one pair per group
                const float* W2 = bowW + l * HBD_ * BD_;
                float a0 = 0.f;
#pragma unroll 8
                for (int o = 0; o < HBD_; o++) a0 += sb[g][o] * W2[o * BD_ + c];
                float bb2 = bowB[l * BD_ + c];
                __syncthreads();
                beta[g][c] = mishf(a0 + bb2);
            } else {
                __syncthreads();
            }
            __syncthreads();
        }
    }
}

// ---------------- K2: q/k projections (per layer), 128 blocks x 4 rows ----------------
__global__ void k_proj(const float* __restrict__ qpW, const float* __restrict__ qpB,
                       const float* __restrict__ kpW, const float* __restrict__ kpB, int l) {
    __shared__ float sx[4][D_];
    int b = blockIdx.x, tid = threadIdx.x;                // 512 threads
    bool isK = (b >= 64);
    int r0 = (b & 63) * 4;
    const float* src = isK ? g_k : g_q;
    const float* W  = (isK ? kpW : qpW) + l * D_ * HD_;
    const float* Bi = (isK ? kpB : qpB) + l * HD_;
    if (tid < 4 * D_) sx[tid >> 6][tid & 63] = src[(r0 + (tid >> 6)) * D_ + (tid & 63)];
    __syncthreads();
    float a0 = 0.f, a1 = 0.f, a2 = 0.f, a3 = 0.f;
#pragma unroll 16
    for (int c = 0; c < D_; c++) {
        float w = W[c * HD_ + tid];
        a0 += sx[0][c] * w;
        a1 += sx[1][c] * w;
        a2 += sx[2][c] * w;
        a3 += sx[3][c] * w;
    }
    float bb = Bi[tid];
    a0 += bb; a1 += bb; a2 += bb; a3 += bb;
    if (isK) {
        g_pk[(r0 + 0) * HD_ + tid] = a0;
        g_pk[(r0 + 1) * HD_ + tid] = a1;
        g_pk[(r0 + 2) * HD_ + tid] = a2;
        g_pk[(r0 + 3) * HD_ + tid] = a3;
        // interleaved transpose: [(dh>>2)*N + j]*4 + (dh&3)
        int base = ((tid >> 2) * N_) * 4 + (tid & 3);
        g_pkTI[base + (r0 + 0) * 4] = a0;
        g_pkTI[base + (r0 + 1) * 4] = a1;
        g_pkTI[base + (r0 + 2) * 4] = a2;
        g_pkTI[base + (r0 + 3) * 4] = a3;
    } else {
        g_pq[(r0 + 0) * HD_ + tid] = a0;
        g_pq[(r0 + 1) * HD_ + tid] = a1;
        g_pq[(r0 + 2) * HD_ + tid] = a2;
        g_pq[(r0 + 3) * HD_ + tid] = a3;
    }
}

// ---------------- K3: attention (blocks 0-127, split-K 512t) + update (128-191, 8 rows) ---
__global__ void k_layer(const float* __restrict__ nt,
                        const float* __restrict__ qoW, const float* __restrict__ qoB,
                        const float* __restrict__ koW, const float* __restrict__ koB,
                        const float* __restrict__ qlnG, const float* __restrict__ qlnB,
                        const float* __restrict__ klnG, const float* __restrict__ klnB,
                        int l, int isLast, float* __restrict__ out) {
    __shared__ __align__(16) char smemRaw[20480];
    int tid = threadIdx.x;                                // 512 threads
    if (blockIdx.x < 128) {
        // ======== attention: (head h, 8-row i tile), dh split across thread halves ========
        float4 (*pqs4)[32]    = (float4(*)[32])smemRaw;               // 4 KB
        float  (*parts)[8][256] = (float(*)[8][256])(smemRaw + 4096); // 16 KB
        int h = blockIdx.x & 3, i0 = (blockIdx.x >> 2) * 8;
        if (isLast && blockIdx.x == 0 && tid == 0) g_pairCount = 0;   // prep next replay
        if (tid < 256)
            pqs4[tid >> 5][tid & 31] =
                ((const float4*)(g_pq + (i0 + (tid >> 5)) * HD_ + h * DH_))[tid & 31];
        __syncthreads();
        int half = tid >> 8, j = tid & 255;
        float acc[8];
#pragma unroll
        for (int ii = 0; ii < 8; ii++) acc[ii] = 0.f;
        const float4* pkt4 = (const float4*)(g_pkTI + (h * (DH_ / 4)) * N_ * 4)
                             + j + half * 16 * N_;
        int qb = half * 16;
#pragma unroll 4
        for (int d4 = 0; d4 < 16; d4++) {
            float4 kv = pkt4[d4 * N_];
#pragma unroll
            for (int ii = 0; ii < 8; ii++) {
                float4 q = pqs4[ii][qb + d4];
                acc[ii] += q.x * kv.x + q.y * kv.y + q.z * kv.z + q.w * kv.w;
            }
        }
#pragma unroll
        for (int ii = 0; ii < 8; ii++) parts[half][ii][j] = acc[ii];
        __syncthreads();
        const float scale = 0.0883883476483184f;          // 1/sqrt(128)
        if (tid < 256) {
            float cd = g_cdiffs[l * H_ + h];
            const float* dptr = g_diffs + (l * H_ + h) * (N_ * N_);
#pragma unroll
            for (int ii = 0; ii < 8; ii++) {
                int pr = (i0 + ii) * N_ + j;
                float dv = g_act[pr] ? dptr[pr] : cd;
                parts[0][ii][j] = (parts[0][ii][j] + parts[1][ii][j]) * scale + dv;
            }
        }
        __syncthreads();
        // warp w (of first 8) owns row i0+w
        int w = tid >> 5, lane = tid & 31;
        if (w < 8) {
            float a[8];
#pragma unroll
            for (int k = 0; k < 8; k++) a[k] = parts[0][w][k * 32 + lane];
            float mx = a[0];
#pragma unroll
            for (int k = 1; k < 8; k++) mx = fmaxf(mx, a[k]);
#pragma unroll
            for (int s = 16; s > 0; s >>= 1) mx = fmaxf(mx, __shfl_xor_sync(0xFFFFFFFFu, mx, s));
            float e[8], ssum = 0.f;
#pragma unroll
            for (int k = 0; k < 8; k++) { e[k] = expf(a[k] - mx); ssum += e[k]; }
#pragma unroll
            for (int s = 16; s > 0; s >>= 1) ssum += __shfl_xor_sync(0xFFFFFFFFu, ssum, s);
            int i = i0 + w;
            float predPrev;
            if (l == 0) predPrev = g_pred0[i];
            else {
                int pb2 = (l & 1) ^ 1;
                predPrev = 0.25f * (g_vals[pb2][0][i] + g_vals[pb2][1][i] +
                                    g_vals[pb2][2][i] + g_vals[pb2][3][i]);
            }
            float vs = 0.f;
#pragma unroll
            for (int k = 0; k < 8; k++) {
                int jj = k * 32 + lane;
                float v = (jj == i) ? predPrev : nt[jj];
                vs += e[k] * v;
            }
#pragma unroll
            for (int s = 16; s > 0; s >>= 1) vs += __shfl_xor_sync(0xFFFFFFFFu, vs, s);
            if (lane == 0) {
                float r = vs / ssum;
                if (isLast) atomicAdd(&out[i], 0.25f * r);
                else        g_vals[l & 1][h][i] = r;
            }
        }
    } else {
        // ======== residual + mish + LayerNorm for q/k, 8 rows per block, 512 threads ======
        float (*sp)[HD_] = (float(*)[HD_])smemRaw;                // 16 KB (flat-permuted)
        float (*srs)[64] = (float(*)[64])(smemRaw + 16384);       // 2 KB
        float (*srq)[64] = (float(*)[64])(smemRaw + 18432);       // 2 KB
        int ub = blockIdx.x - 128;
        bool isK = (ub >= 32);
        int r0 = (ub & 31) * 8;
        const float* P  = isK ? g_pk : g_pq;
        const float* W  = (isK ? koW : qoW) + l * HD_ * D_;
        const float* Bi = (isK ? koB : qoB) + l * D_;
        const float* G  = (isK ? klnG : qlnG) + l * D_;
        const float* Bt = (isK ? klnB : qlnB) + l * D_;
        float* dst = isK ? g_k : g_q;
        // permuted fill: sp[r][m] = flat[m] = P[r, (m&3)*128 + (m>>2)]
        for (int idx = tid; idx < 8 * HD_; idx += 512) {
            int r = idx >> 9, s = idx & 511;
            int m = ((s & 127) << 2) | (s >> 7);
            sp[r][m] = P[(r0 + r) * HD_ + s];
        }
        __syncthreads();
        int r = tid >> 6, c = tid & 63;
        float acc = 0.f;
        const float4* sp4 = (const float4*)sp[r];
        const float* wc = W + c;
#pragma unroll 4
        for (int m4 = 0; m4 < 128; m4++) {
            float4 pv = sp4[m4];
            const float* wb = wc + (4 * m4) * D_;
            acc += pv.x * wb[0] + pv.y * wb[D_] + pv.z * wb[2 * D_] + pv.w * wb[3 * D_];
        }
        float y = dst[(r0 + r) * D_ + c] + mishf(acc + Bi[c]);
        srs[r][c] = y;
        srq[r][c] = y * y;
        __syncthreads();
        for (int s = 32; s > 0; s >>= 1) {
            if (c < s) { srs[r][c] += srs[r][c + s]; srq[r][c] += srq[r][c + s]; }
            __syncthreads();
        }
        float mean = srs[r][0] * (1.0f / 64.0f);
        float var  = srq[r][0] * (1.0f / 64.0f) - mean * mean;
        float o    = (y - mean) * rsqrtf(var + EPS_) * G[c] + Bt[c];
        dst[(r0 + r) * D_ + c] = o;
    }
}

// ---------------- launch ----------------
extern "C" void kernel_launch(void* const* d_in, const int* in_sizes, int n_in,
                              void* d_out, int out_size) {
    const float* X     = (const float*)d_in[0];
    const float* E     = (const float*)d_in[1];
    const float* nt    = (const float*)d_in[2];
    const float* embW  = (const float*)d_in[3];
    const float* embB  = (const float*)d_in[4];
    const float* boutW = (const float*)d_in[5];
    const float* boutB = (const float*)d_in[6];
    const float* qpW   = (const float*)d_in[7];
    const float* qpB   = (const float*)d_in[8];
    const float* kpW   = (const float*)d_in[9];
    const float* kpB   = (const float*)d_in[10];
    const float* qoW   = (const float*)d_in[11];
    const float* qoB   = (const float*)d_in[12];
    const float* koW   = (const float*)d_in[13];
    const float* koB   = (const float*)d_in[14];
    const float* bpW   = (const float*)d_in[15];
    const float* bpB   = (const float*)d_in[16];
    const float* bowW  = (const float*)d_in[17];
    const float* bowB  = (const float*)d_in[18];
    const float* qlnG  = (const float*)d_in[19];
    const float* qlnB  = (const float*)d_in[20];
    const float* klnG  = (const float*)d_in[21];
    const float* klnB  = (const float*)d_in[22];
    float* out = (float*)d_out;

    k_initdist<<<N_, 256>>>(X, E, embW, embB, boutW, boutB, out);
    k_active<<<96, 512>>>(bpW, bpB, bowW, bowB);
    for (int l = 0; l < L_; l++) {
        int isLast = (l == L_ - 1);
        k_proj<<<128, 512>>>(qpW, qpB, kpW, kpB, l);
        k_layer<<<isLast ? 128 : 192, 512>>>(nt, qoW, qoB, koW, koB,
                                             qlnG, qlnB, klnG, klnB, l, isLast, out);
    }
}

// round 10
// speedup vs baseline: 2.3391x; 1.0209x over previous
#include <cuda_runtime.h>
#include <math.h>

#define N_   256
#define FB_  256
#define D_   64
#define H_   4
#define DH_  128
#define HD_  512   // H*DH
#define BD_  128
#define HBD_ 512   // H*BD
#define AK_  100
#define L_   4
#define EPS_ 1e-5f
#define G_   192   // persistent grid size (must all be co-resident)

// ---------------- scratch (device globals; zero-init, no allocations) ----------------
__device__ float g_d[N_ * N_];
__device__ unsigned char g_act[N_ * N_];
__device__ int   g_pairCount;                  // reset at end of replay for next replay
__device__ int   g_pairList[N_ * N_];
__device__ float g_diffs[L_ * H_ * N_ * N_];   // only active entries written/read
__device__ float g_cdiffs[L_ * H_];
__device__ float g_q[N_ * D_];
__device__ float g_k[N_ * D_];
__device__ float g_pred0[N_];
__device__ float g_pq[N_ * HD_];
__device__ float g_pk[N_ * HD_];
__device__ float g_pkTI[HD_ / 4 * N_ * 4];     // interleaved: [((h*32+d4)*N + j)*4 + (dh&3)]
__device__ float g_vals[2][H_][N_];
__device__ unsigned g_barArrive;               // software grid barrier state
__device__ unsigned g_barGen;

__device__ __forceinline__ float mishf(float x) {
    float sp = (x > 20.f) ? x : log1pf(expf(x));
    return x * tanhf(sp);
}

// Grid-wide barrier. Safe because launch_bounds guarantees all G_ blocks co-resident.
// gpu-scope __threadfence emits CCTL.IVALL on sm_103a -> L1 invalidate gives acquire.
__device__ __forceinline__ void gridBar() {
    __threadfence();                           // release: flush my writes to L2
    __syncthreads();
    if (threadIdx.x == 0) {
        unsigned gen = __ldcg(&g_barGen);
        unsigned t = atomicAdd(&g_barArrive, 1u);
        if (t == G_ - 1) {
            g_barArrive = 0u;
            __threadfence();
            atomicExch(&g_barGen, gen + 1u);
        } else {
            while (__ldcg(&g_barGen) == gen) __nanosleep(32);
        }
    }
    __syncthreads();
    __threadfence();                           // acquire: invalidate stale L1 lines
}

__global__ __launch_bounds__(512, 2)
void k_mega(const float* __restrict__ X, const float* __restrict__ E,
            const float* __restrict__ nt,
            const float* __restrict__ embW, const float* __restrict__ embB,
            const float* __restrict__ boutW, const float* __restrict__ boutB,
            const float* __restrict__ qpW, const float* __restrict__ qpB,
            const float* __restrict__ kpW, const float* __restrict__ kpB,
            const float* __restrict__ qoW, const float* __restrict__ qoB,
            const float* __restrict__ koW, const float* __restrict__ koB,
            const float* __restrict__ bpW, const float* __restrict__ bpB,
            const float* __restrict__ bowW, const float* __restrict__ bowB,
            const float* __restrict__ qlnG, const float* __restrict__ qlnB,
            const float* __restrict__ klnG, const float* __restrict__ klnB,
            float* __restrict__ out) {
    __shared__ __align__(16) char sm[20992];
    int b = blockIdx.x, tid = threadIdx.x;     // 512 threads

    // ================= P0: embedding + pred0 + distances + out zero =================
    if (b < 128) {
        int half = tid >> 8, t = tid & 255;
        char* hb = sm + half * 2560;
        float* sx   = (float*)hb;              // 256 floats
        float* se   = (float*)(hb + 1024);     // 104 floats
        float* red  = (float*)(hb + 1440);     // 256 floats
        float* wred = (float*)(hb + 2464);     // 8 floats
        int i = 2 * b + half;
        sx[t] = X[i * FB_ + t];
        if (t < AK_) se[t] = E[i * AK_ + t];
        if (t == 0) out[i] = 0.f;
        __syncthreads();
        // distances
        float sqd = 0.f;
        const float* Ej = E + t * AK_;
#pragma unroll 4
        for (int a = 0; a < AK_; a++) { float d = se[a] - Ej[a]; sqd += d * d; }
        float dd = (sqd > 0.f) ? sqrtf(sqd) : 0.f;
        g_d[i * N_ + t] = dd;
        // d > 2 => every RBF term exp(< -127) == exactly 0.0f in fp32 (same as reference)
        bool act = (dd <= 2.0f);
        g_act[i * N_ + t] = act ? 1 : 0;
        if (act) {
            int p = atomicAdd(&g_pairCount, 1);
            g_pairList[p] = i * N_ + t;
        }
        // embedding
        {
            int c = t & 63, part = t >> 6;
            float acc = 0.f;
            const float* wp = embW + (part * 64) * D_ + c;
#pragma unroll 16
            for (int f = 0; f < 64; f++) acc += sx[part * 64 + f] * wp[f * D_];
            red[t] = acc;
        }
        __syncthreads();
        if (t < D_) {
            float v = red[t] + red[t + 64] + red[t + 128] + red[t + 192] + embB[t];
            g_q[i * D_ + t] = v;
            g_k[i * D_ + t] = v;
        }
        float pacc = sx[t] * boutW[t];
#pragma unroll
        for (int s = 16; s > 0; s >>= 1) pacc += __shfl_xor_sync(0xFFFFFFFFu, pacc, s);
        if ((t & 31) == 0) wred[t >> 5] = pacc;
        __syncthreads();
        if (t == 0) {
            float s = 0.f;
#pragma unroll
            for (int w = 0; w < 8; w++) s += wred[w];
            g_pred0[i] = s + boutB[0];
        }
    }
    gridBar();

    // ================= P1: bias pipeline, 4 pairs/chunk, virtual pair 0 = const ======
    {
        float (*beta)[BD_] = (float(*)[BD_])sm;                  // 2 KB
        float (*sb)[HBD_]  = (float(*)[HBD_])(sm + 2048);        // 8 KB
        int*   svp         = (int*)(sm + 10240);
        float* sd          = (float*)(sm + 10256);
        int total = g_pairCount + 1;
        int nChunks = (total + 3) >> 2;
        for (int ch = b; ch < nChunks; ch += G_) {
            int pbase = ch << 2;
            int np = total - pbase; if (np > 4) np = 4;
            if (tid < 4) {
                int vp = pbase + tid;
                if (tid < np) {
                    if (vp == 0) { svp[tid] = -1; sd[tid] = 0.f; }      // constant path
                    else { int pr = g_pairList[vp - 1]; svp[tid] = pr; sd[tid] = g_d[pr]; }
                } else { svp[tid] = -2; sd[tid] = 0.f; }
            }
            __syncthreads();
            {
                int p = tid >> 7, c = tid & 127;
                float ddv = sd[p] - (float)c * (1.0f / 127.0f);
                beta[p][c] = (p < np && svp[p] >= 0) ? expf(-127.0f * ddv * ddv) : 0.f;
            }
            __syncthreads();
            for (int l = 0; l < L_; l++) {
                const float* W = bpW + l * BD_ * HBD_;
                float acc0 = 0.f, acc1 = 0.f, acc2 = 0.f, acc3 = 0.f;
#pragma unroll 8
                for (int c = 0; c < BD_; c++) {
                    float w = W[c * HBD_ + tid];
                    acc0 += beta[0][c] * w;
                    acc1 += beta[1][c] * w;
                    acc2 += beta[2][c] * w;
                    acc3 += beta[3][c] * w;
                }
                float bb = bpB[l * HBD_ + tid];
                sb[0][tid] = acc0 + bb;
                sb[1][tid] = acc1 + bb;
                sb[2][tid] = acc2 + bb;
                sb[3][tid] = acc3 + bb;
                __syncthreads();
                if (tid < 16) {
                    int p = tid >> 2, h = tid & 3;
                    if (p < np && svp[p] != -2) {
                        float s = 0.f;
#pragma unroll 8
                        for (int bd = 0; bd < BD_; bd++) { float v = sb[p][h * BD_ + bd]; s += v * v; }
                        float r = sqrtf(s);
                        if (svp[p] == -1) g_cdiffs[l * H_ + h] = r;
                        else              g_diffs[(l * H_ + h) * (N_ * N_) + svp[p]] = r;
                    }
                }
                if (l < L_ - 1) {
                    int c = tid & 127, g = tid >> 7;
                    const float* W2 = bowW + l * HBD_ * BD_;
                    float a0 = 0.f;
#pragma unroll 8
                    for (int o = 0; o < HBD_; o++) a0 += sb[g][o] * W2[o * BD_ + c];
                    float bb2 = bowB[l * BD_ + c];
                    __syncthreads();
                    beta[g][c] = mishf(a0 + bb2);
                } else {
                    __syncthreads();
                }
                __syncthreads();
            }
        }
    }
    gridBar();

    // ================= per-layer: proj -> bar -> attn || update -> bar ===============
    for (int l = 0; l < L_; l++) {
        // -------- projection (blocks 0..127, 4 rows each) --------
        if (b < 128) {
            float (*sx)[D_] = (float(*)[D_])sm;                  // 1 KB
            bool isK = (b >= 64);
            int r0 = (b & 63) * 4;
            const float* src = isK ? g_k : g_q;
            const float* W  = (isK ? kpW : qpW) + l * D_ * HD_;
            const float* Bi = (isK ? kpB : qpB) + l * HD_;
            if (tid < 4 * D_) sx[tid >> 6][tid & 63] = src[(r0 + (tid >> 6)) * D_ + (tid & 63)];
            __syncthreads();
            float a0 = 0.f, a1 = 0.f, a2 = 0.f, a3 = 0.f;
#pragma unroll 16
            for (int c = 0; c < D_; c++) {
                float w = W[c * HD_ + tid];
                a0 += sx[0][c] * w;
                a1 += sx[1][c] * w;
                a2 += sx[2][c] * w;
                a3 += sx[3][c] * w;
            }
            float bb = Bi[tid];
            a0 += bb; a1 += bb; a2 += bb; a3 += bb;
            if (isK) {
                g_pk[(r0 + 0) * HD_ + tid] = a0;
                g_pk[(r0 + 1) * HD_ + tid] = a1;
                g_pk[(r0 + 2) * HD_ + tid] = a2;
                g_pk[(r0 + 3) * HD_ + tid] = a3;
                int base = ((tid >> 2) * N_) * 4 + (tid & 3);
                g_pkTI[base + (r0 + 0) * 4] = a0;
                g_pkTI[base + (r0 + 1) * 4] = a1;
                g_pkTI[base + (r0 + 2) * 4] = a2;
                g_pkTI[base + (r0 + 3) * 4] = a3;
            } else {
                g_pq[(r0 + 0) * HD_ + tid] = a0;
                g_pq[(r0 + 1) * HD_ + tid] = a1;
                g_pq[(r0 + 2) * HD_ + tid] = a2;
                g_pq[(r0 + 3) * HD_ + tid] = a3;
            }
        }
        gridBar();
        int isLast = (l == L_ - 1);
        if (b < 128) {
            // -------- attention: (head h, 8-row tile), split-K across thread halves --
            float4 (*pqs4)[32]      = (float4(*)[32])sm;                 // 4 KB
            float  (*parts)[8][256] = (float(*)[8][256])(sm + 4096);     // 16 KB
            int h = b & 3, i0 = (b >> 2) * 8;
            if (tid < 256)
                pqs4[tid >> 5][tid & 31] =
                    ((const float4*)(g_pq + (i0 + (tid >> 5)) * HD_ + h * DH_))[tid & 31];
            __syncthreads();
            int half = tid >> 8, j = tid & 255;
            float acc[8];
#pragma unroll
            for (int ii = 0; ii < 8; ii++) acc[ii] = 0.f;
            const float4* pkt4 = (const float4*)(g_pkTI + (h * (DH_ / 4)) * N_ * 4)
                                 + j + half * 16 * N_;
            int qb = half * 16;
#pragma unroll 4
            for (int d4 = 0; d4 < 16; d4++) {
                float4 kv = pkt4[d4 * N_];
#pragma unroll
                for (int ii = 0; ii < 8; ii++) {
                    float4 q = pqs4[ii][qb + d4];
                    acc[ii] += q.x * kv.x + q.y * kv.y + q.z * kv.z + q.w * kv.w;
                }
            }
#pragma unroll
            for (int ii = 0; ii < 8; ii++) parts[half][ii][j] = acc[ii];
            __syncthreads();
            const float scale = 0.0883883476483184f;   // 1/sqrt(128)
            if (tid < 256) {
                float cd = g_cdiffs[l * H_ + h];
                const float* dptr = g_diffs + (l * H_ + h) * (N_ * N_);
#pragma unroll
                for (int ii = 0; ii < 8; ii++) {
                    int pr = (i0 + ii) * N_ + j;
                    float dv = g_act[pr] ? dptr[pr] : cd;
                    parts[0][ii][j] = (parts[0][ii][j] + parts[1][ii][j]) * scale + dv;
                }
            }
            __syncthreads();
            int w = tid >> 5, lane = tid & 31;
            if (w < 8) {                              // warp w owns row i0+w
                float a[8];
#pragma unroll
                for (int k = 0; k < 8; k++) a[k] = parts[0][w][k * 32 + lane];
                float mx = a[0];
#pragma unroll
                for (int k = 1; k < 8; k++) mx = fmaxf(mx, a[k]);
#pragma unroll
                for (int s = 16; s > 0; s >>= 1) mx = fmaxf(mx, __shfl_xor_sync(0xFFFFFFFFu, mx, s));
                float e[8], ssum = 0.f;
#pragma unroll
                for (int k = 0; k < 8; k++) { e[k] = expf(a[k] - mx); ssum += e[k]; }
#pragma unroll
                for (int s = 16; s > 0; s >>= 1) ssum += __shfl_xor_sync(0xFFFFFFFFu, ssum, s);
                int i = i0 + w;
                float predPrev;
                if (l == 0) predPrev = g_pred0[i];
                else {
                    int pb2 = (l & 1) ^ 1;
                    predPrev = 0.25f * (g_vals[pb2][0][i] + g_vals[pb2][1][i] +
                                        g_vals[pb2][2][i] + g_vals[pb2][3][i]);
                }
                float vs = 0.f;
#pragma unroll
                for (int k = 0; k < 8; k++) {
                    int jj = k * 32 + lane;
                    float v = (jj == i) ? predPrev : nt[jj];
                    vs += e[k] * v;
                }
#pragma unroll
                for (int s = 16; s > 0; s >>= 1) vs += __shfl_xor_sync(0xFFFFFFFFu, vs, s);
                if (lane == 0) {
                    float r = vs / ssum;
                    if (isLast) atomicAdd(&out[i], 0.25f * r);
                    else        g_vals[l & 1][h][i] = r;
                }
            }
        } else if (!isLast) {
            // -------- residual + mish + LayerNorm for q/k, 8 rows per block ----------
            float (*sp)[HD_] = (float(*)[HD_])sm;                // 16 KB (flat-permuted)
            float (*srs)[64] = (float(*)[64])(sm + 16384);       // 2 KB
            float (*srq)[64] = (float(*)[64])(sm + 18432);       // 2 KB
            int ub = b - 128;
            bool isK = (ub >= 32);
            int r0 = (ub & 31) * 8;
            const float* P  = isK ? g_pk : g_pq;
            const float* W  = (isK ? koW : qoW) + l * HD_ * D_;
            const float* Bi = (isK ? koB : qoB) + l * D_;
            const float* G  = (isK ? klnG : qlnG) + l * D_;
            const float* Bt = (isK ? klnB : qlnB) + l * D_;
            float* dst = isK ? g_k : g_q;
            for (int idx = tid; idx < 8 * HD_; idx += 512) {
                int r = idx >> 9, s = idx & 511;
                int m = ((s & 127) << 2) | (s >> 7);
                sp[r][m] = P[(r0 + r) * HD_ + s];
            }
            __syncthreads();
            int r = tid >> 6, c = tid & 63;
            float acc = 0.f;
            const float4* sp4 = (const float4*)sp[r];
            const float* wc = W + c;
#pragma unroll 4
            for (int m4 = 0; m4 < 128; m4++) {
                float4 pv = sp4[m4];
                const float* wb = wc + (4 * m4) * D_;
                acc += pv.x * wb[0] + pv.y * wb[D_] + pv.z * wb[2 * D_] + pv.w * wb[3 * D_];
            }
            float y = dst[(r0 + r) * D_ + c] + mishf(acc + Bi[c]);
            srs[r][c] = y;
            srq[r][c] = y * y;
            __syncthreads();
            for (int s = 32; s > 0; s >>= 1) {
                if (c < s) { srs[r][c] += srs[r][c + s]; srq[r][c] += srq[r][c + s]; }
                __syncthreads();
            }
            float mean = srs[r][0] * (1.0f / 64.0f);
            float var  = srq[r][0] * (1.0f / 64.0f) - mean * mean;
            float o    = (y - mean) * rsqrtf(var + EPS_) * G[c] + Bt[c];
            dst[(r0 + r) * D_ + c] = o;
        }
        if (isLast) {
            if (b == 0 && tid == 0) g_pairCount = 0;   // prep next replay
        } else {
            gridBar();
        }
    }
}

// ---------------- launch ----------------
extern "C" void kernel_launch(void* const* d_in, const int* in_sizes, int n_in,
                              void* d_out, int out_size) {
    const float* X     = (const float*)d_in[0];
    const float* E     = (const float*)d_in[1];
    const float* nt    = (const float*)d_in[2];
    const float* embW  = (const float*)d_in[3];
    const float* embB  = (const float*)d_in[4];
    const float* boutW = (const float*)d_in[5];
    const float* boutB = (const float*)d_in[6];
    const float* qpW   = (const float*)d_in[7];
    const float* qpB   = (const float*)d_in[8];
    const float* kpW   = (const float*)d_in[9];
    const float* kpB   = (const float*)d_in[10];
    const float* qoW   = (const float*)d_in[11];
    const float* qoB   = (const float*)d_in[12];
    const float* koW   = (const float*)d_in[13];
    const float* koB   = (const float*)d_in[14];
    const float* bpW   = (const float*)d_in[15];
    const float* bpB   = (const float*)d_in[16];
    const float* bowW  = (const float*)d_in[17];
    const float* bowB  = (const float*)d_in[18];
    const float* qlnG  = (const float*)d_in[19];
    const float* qlnB  = (const float*)d_in[20];
    const float* klnG  = (const float*)d_in[21];
    const float* klnB  = (const float*)d_in[22];
    float* out = (float*)d_out;

    k_mega<<<G_, 512>>>(X, E, nt, embW, embB, boutW, boutB,
                        qpW, qpB, kpW, kpB, qoW, qoB, koW, koB,
                        bpW, bpB, bowW, bowB, qlnG, qlnB, klnG, klnB, out);
}

// round 11
// speedup vs baseline: 2.4538x; 1.0490x over previous
#include <cuda_runtime.h>
#include <math.h>

#define N_   256
#define FB_  256
#define D_   64
#define H_   4
#define DH_  128
#define HD_  512
#define BD_  128
#define HBD_ 512
#define AK_  100
#define L_   4
#define EPS_ 1e-5f
#define G_   192   // persistent grid; all blocks co-resident (2/SM guaranteed)

// ---------------- scratch (device globals; zero-init, no allocations) ----------------
__device__ float g_d[N_ * N_];
__device__ unsigned char g_act[N_ * N_];
__device__ int   g_pairCount;
__device__ int   g_pairList[N_ * N_];
__device__ float g_diffs[L_ * H_ * N_ * N_];
__device__ float g_cdiffs[L_ * H_];
__device__ float g_q[N_ * D_];
__device__ float g_k[N_ * D_];
__device__ float g_pred0[N_];
__device__ float g_At[L_ * H_ * D_ * D_];      // [l][h][d][c] = Wq_h Wk_h^T / sqrt(DH)
__device__ float g_M[L_ * 2 * D_ * D_];        // [l][qk][d][c] effective update matrix
__device__ float g_v[L_ * 2 * D_];             // effective update bias
__device__ float g_bt[L_ * H_ * D_];           // [l][h][c] = Wk_h @ qpB_h / sqrt(DH)
__device__ float g_B[2 * H_ * N_ * D_];        // parity  [p][h][i][c]
__device__ float4 g_kT4[2 * 16 * N_];          // parity  [p][d4][j] (4 dh comps)
__device__ float g_colK[2 * H_ * N_];          // parity  [p][h][j]
__device__ float g_u[2 * N_ * D_];             // [qk][row][c] update pre-activation
__device__ float g_vals[2][H_][N_];
__device__ unsigned g_barArrive;
__device__ unsigned g_barGen;

__device__ __forceinline__ float mishf(float x) {
    float sp = (x > 20.f) ? x : log1pf(expf(x));
    return x * tanhf(sp);
}

__device__ __forceinline__ void gridBar() {
    __threadfence();
    __syncthreads();
    if (threadIdx.x == 0) {
        unsigned gen = __ldcg(&g_barGen);
        unsigned t = atomicAdd(&g_barArrive, 1u);
        if (t == G_ - 1) {
            g_barArrive = 0u;
            __threadfence();
            atomicExch(&g_barGen, gen + 1u);
        } else {
            while (__ldcg(&g_barGen) == gen) __nanosleep(32);
        }
    }
    __syncthreads();
    __threadfence();
}

__global__ __launch_bounds__(512, 2)
void k_mega(const float* __restrict__ X, const float* __restrict__ E,
            const float* __restrict__ nt,
            const float* __restrict__ embW, const float* __restrict__ embB,
            const float* __restrict__ boutW, const float* __restrict__ boutB,
            const float* __restrict__ qpW, const float* __restrict__ qpB,
            const float* __restrict__ kpW, const float* __restrict__ kpB,
            const float* __restrict__ qoW, const float* __restrict__ qoB,
            const float* __restrict__ koW, const float* __restrict__ koB,
            const float* __restrict__ bpW, const float* __restrict__ bpB,
            const float* __restrict__ bowW, const float* __restrict__ bowB,
            const float* __restrict__ qlnG, const float* __restrict__ qlnB,
            const float* __restrict__ klnG, const float* __restrict__ klnB,
            float* __restrict__ out) {
    __shared__ __align__(16) char sm[20608];
    int b = blockIdx.x, tid = threadIdx.x;     // 512 threads

    // ============ Phase 0: blocks 0-127: embed/pred0/dist ; 128-191: PRE ============
    if (b < 128) {
        int half = tid >> 8, t = tid & 255;
        char* hb = sm + half * 2560;
        float* sx   = (float*)hb;
        float* se   = (float*)(hb + 1024);
        float* red  = (float*)(hb + 1440);
        float* wred = (float*)(hb + 2464);
        int i = 2 * b + half;
        sx[t] = X[i * FB_ + t];
        if (t < AK_) se[t] = E[i * AK_ + t];
        if (t == 0) out[i] = 0.f;
        __syncthreads();
        float sqd = 0.f;
        const float* Ej = E + t * AK_;
#pragma unroll 4
        for (int a = 0; a < AK_; a++) { float d = se[a] - Ej[a]; sqd += d * d; }
        float dd = (sqd > 0.f) ? sqrtf(sqd) : 0.f;
        g_d[i * N_ + t] = dd;
        // d > 2 => every RBF term exp(< -127) == exactly 0.0f in fp32 (same as reference)
        bool act = (dd <= 2.0f);
        g_act[i * N_ + t] = act ? 1 : 0;
        if (act) {
            int p = atomicAdd(&g_pairCount, 1);
            g_pairList[p] = i * N_ + t;
        }
        {
            int c = t & 63, part = t >> 6;
            float acc = 0.f;
            const float* wp = embW + (part * 64) * D_ + c;
#pragma unroll 16
            for (int f = 0; f < 64; f++) acc += sx[part * 64 + f] * wp[f * D_];
            red[t] = acc;
        }
        __syncthreads();
        if (t < D_) {
            float v = red[t] + red[t + 64] + red[t + 128] + red[t + 192] + embB[t];
            g_q[i * D_ + t] = v;
            g_k[i * D_ + t] = v;
        }
        float pacc = sx[t] * boutW[t];
#pragma unroll
        for (int s = 16; s > 0; s >>= 1) pacc += __shfl_xor_sync(0xFFFFFFFFu, pacc, s);
        if ((t & 31) == 0) wred[t >> 5] = pacc;
        __syncthreads();
        if (t == 0) {
            float s = 0.f;
#pragma unroll
            for (int w = 0; w < 8; w++) s += wred[w];
            g_pred0[i] = s + boutB[0];
        }
    } else {
        int bt = b - 128;
        int c = tid & 63, rg = tid >> 6;
        if (bt < 16) {
            // ---- Atilde (l,h) + col-bias b~ ----
            int l = bt >> 2, h = bt & 3;
            float (*smK)[65] = (float(*)[65])sm;
            float acc[8];
#pragma unroll
            for (int u = 0; u < 8; u++) acc[u] = 0.f;
            float bacc = 0.f;
            for (int d0 = 0; d0 < DH_; d0 += 64) {
                __syncthreads();
                for (int idx = tid; idx < 4096; idx += 512) {
                    int cc = idx >> 6, d = idx & 63;
                    smK[cc][d] = kpW[l * (D_ * HD_) + cc * HD_ + h * DH_ + d0 + d];
                }
                __syncthreads();
                const float* qp = qpW + l * (D_ * HD_) + h * DH_ + d0;
                const float* qb = qpB + l * HD_ + h * DH_ + d0;
#pragma unroll 4
                for (int d = 0; d < 64; d++) {
                    float w = smK[c][d];
#pragma unroll
                    for (int u = 0; u < 8; u++) acc[u] += qp[(rg * 8 + u) * HD_ + d] * w;
                    if (rg == 0) bacc += w * qb[d];
                }
            }
            const float s = 0.08838834764831843f;  // 1/sqrt(128)
#pragma unroll
            for (int u = 0; u < 8; u++)
                g_At[((l * H_ + h) * D_ + rg * 8 + u) * D_ + c] = acc[u] * s;
            if (rg == 0) g_bt[(l * H_ + h) * D_ + c] = bacc * s;
        } else if (bt < 24) {
            // ---- M (l,qk) + v ----
            int l = (bt - 16) >> 1, qk = (bt - 16) & 1;
            const float* Wp  = (qk ? kpW : qpW) + l * D_ * HD_;
            const float* WpB = (qk ? kpB : qpB) + l * HD_;
            const float* Wo  = (qk ? koW : qoW) + l * HD_ * D_;
            const float* WoB = (qk ? koB : qoB) + l * D_;
            float (*smP)[65] = (float(*)[65])sm;
            float acc[8];
#pragma unroll
            for (int u = 0; u < 8; u++) acc[u] = 0.f;
            float vacc = 0.f;
            for (int s0 = 0; s0 < HD_; s0 += 64) {
                __syncthreads();
                for (int idx = tid; idx < 4096; idx += 512) {
                    int dd = idx >> 6, ss = idx & 63;
                    smP[dd][ss] = Wp[dd * HD_ + s0 + ss];
                }
                __syncthreads();
#pragma unroll 4
                for (int ss = 0; ss < 64; ss++) {
                    int s = s0 + ss;
                    int m = ((s & 127) << 2) | (s >> 7);   // inverse head/dh permutation
                    float w = Wo[m * D_ + c];
#pragma unroll
                    for (int u = 0; u < 8; u++) acc[u] += smP[rg * 8 + u][ss] * w;
                    if (rg == 0) vacc += WpB[s] * w;
                }
            }
#pragma unroll
            for (int u = 0; u < 8; u++)
                g_M[((l * 2 + qk) * D_ + rg * 8 + u) * D_ + c] = acc[u];
            if (rg == 0) g_v[(l * 2 + qk) * D_ + c] = vacc + WoB[c];
        }
    }
    gridBar();

    // ============ Phase 1: blocks 0-63: bias pipeline ; 128-191: A_0 ============
    if (b < 64) {
        float (*beta)[BD_] = (float(*)[BD_])sm;                 // 4 KB
        float (*sb)[HBD_]  = (float(*)[HBD_])(sm + 4096);       // 16 KB
        int*   svp         = (int*)(sm + 20480);
        float* sd          = (float*)(sm + 20512);
        int total = g_pairCount + 1;
        int nChunks = (total + 7) >> 3;
        for (int ch = b; ch < nChunks; ch += 64) {
            int pbase = ch << 3;
            int np = total - pbase; if (np > 8) np = 8;
            if (tid < 8) {
                int vp = pbase + tid;
                if (tid < np) {
                    if (vp == 0) { svp[tid] = -1; sd[tid] = 0.f; }
                    else { int pr = g_pairList[vp - 1]; svp[tid] = pr; sd[tid] = g_d[pr]; }
                } else { svp[tid] = -2; sd[tid] = 0.f; }
            }
            __syncthreads();
            for (int idx = tid; idx < 8 * BD_; idx += 512) {
                int p = idx >> 7, c = idx & 127;
                float ddv = sd[p] - (float)c * (1.0f / 127.0f);
                beta[p][c] = (p < np && svp[p] >= 0) ? expf(-127.0f * ddv * ddv) : 0.f;
            }
            __syncthreads();
            for (int l = 0; l < L_; l++) {
                const float* W = bpW + l * BD_ * HBD_;
                float acc[8];
#pragma unroll
                for (int p = 0; p < 8; p++) acc[p] = 0.f;
#pragma unroll 8
                for (int c = 0; c < BD_; c++) {
                    float w = W[c * HBD_ + tid];
#pragma unroll
                    for (int p = 0; p < 8; p++) acc[p] += beta[p][c] * w;
                }
                float bb = bpB[l * HBD_ + tid];
#pragma unroll
                for (int p = 0; p < 8; p++) sb[p][tid] = acc[p] + bb;
                __syncthreads();
                if (tid < 32) {
                    int p = tid >> 2, h = tid & 3;
                    if (p < np && svp[p] != -2) {
                        float s = 0.f;
#pragma unroll 8
                        for (int bd = 0; bd < BD_; bd++) { float v = sb[p][h * BD_ + bd]; s += v * v; }
                        float r = sqrtf(s);
                        if (svp[p] == -1) g_cdiffs[l * H_ + h] = r;
                        else              g_diffs[(l * H_ + h) * (N_ * N_) + svp[p]] = r;
                    }
                }
                if (l < L_ - 1) {
                    int c = tid & 127, g = tid >> 7;
                    const float* W2 = bowW + l * HBD_ * BD_;
                    float a0 = 0.f, a1 = 0.f;
#pragma unroll 8
                    for (int o = 0; o < HBD_; o++) {
                        float w = W2[o * BD_ + c];
                        a0 += sb[g][o] * w;
                        a1 += sb[g + 4][o] * w;
                    }
                    float bb2 = bowB[l * BD_ + c];
                    __syncthreads();
                    beta[g][c]     = mishf(a0 + bb2);
                    beta[g + 4][c] = mishf(a1 + bb2);
                }
                __syncthreads();
            }
            __syncthreads();
        }
    } else if (b >= 128) {
        // -------- A_0: no update; build B/u/colK/kT for layer 0 (parity 0) --------
        float (*sq)[D_] = (float(*)[D_])sm;
        int ab = b - 128; bool isK = ab >= 32; int r0 = (ab & 31) * 8;
        const float* x = isK ? g_k : g_q;
        int rr = tid >> 6, c = tid & 63, row = r0 + rr;
        sq[rr][c] = x[row * D_ + c];
        __syncthreads();
        const int l = 0, p = 0;
        if (!isK) {
            const float* A0 = g_At + ((l * H_ + 0) * D_) * D_;
            const float* A1 = g_At + ((l * H_ + 1) * D_) * D_;
            const float* A2 = g_At + ((l * H_ + 2) * D_) * D_;
            const float* A3 = g_At + ((l * H_ + 3) * D_) * D_;
            const float* Mq = g_M + (l * 2 + 0) * D_ * D_;
            float b0 = 0, b1 = 0, b2 = 0, b3 = 0, au = 0;
#pragma unroll 8
            for (int d = 0; d < D_; d++) {
                float qv = sq[rr][d];
                b0 += qv * A0[d * D_ + c];
                b1 += qv * A1[d * D_ + c];
                b2 += qv * A2[d * D_ + c];
                b3 += qv * A3[d * D_ + c];
                au += qv * Mq[d * D_ + c];
            }
            g_B[((p * H_ + 0) * N_ + row) * D_ + c] = b0;
            g_B[((p * H_ + 1) * N_ + row) * D_ + c] = b1;
            g_B[((p * H_ + 2) * N_ + row) * D_ + c] = b2;
            g_B[((p * H_ + 3) * N_ + row) * D_ + c] = b3;
            g_u[0 * N_ * D_ + row * D_ + c] = au + g_v[(l * 2 + 0) * D_ + c];
        } else {
            const float* Mk = g_M + (l * 2 + 1) * D_ * D_;
            float au = 0;
#pragma unroll 8
            for (int d = 0; d < D_; d++) au += sq[rr][d] * Mk[d * D_ + c];
            g_u[1 * N_ * D_ + row * D_ + c] = au + g_v[(l * 2 + 1) * D_ + c];
            ((float*)g_kT4)[((p * 16 + (c >> 2)) * N_ + row) * 4 + (c & 3)] = sq[rr][c];
            if (c < 4) {
                const float* bt = g_bt + (l * H_ + c) * D_;
                float s = 0.f;
#pragma unroll 8
                for (int d = 0; d < D_; d++) s += sq[rr][d] * bt[d];
                g_colK[(p * H_ + c) * N_ + row] = s;
            }
        }
    }
    gridBar();

    // ============ layer loop: attn_l (0-127) || A_{l+1} (128-191) ============
    for (int l = 0; l < L_; l++) {
        int isLast = (l == L_ - 1);
        int p = l & 1;
        if (b < 128) {
            // -------- attention (head h, 8-row tile), depth 64 split over halves ----
            float (*sB)[D_]   = (float(*)[D_])sm;                     // 2 KB
            float4 (*sB4)[16] = (float4(*)[16])sm;
            float (*parts)[8][256] = (float(*)[8][256])(sm + 2048);   // 16 KB
            int h = b & 3, i0 = (b >> 2) * 8;
            sB[tid >> 6][tid & 63] =
                g_B[((p * H_ + h) * N_ + i0 + (tid >> 6)) * D_ + (tid & 63)];
            __syncthreads();
            int half = tid >> 8, j = tid & 255;
            float acc[8];
#pragma unroll
            for (int ii = 0; ii < 8; ii++) acc[ii] = 0.f;
            const float4* kt = g_kT4 + (p * 16 + half * 8) * N_ + j;
#pragma unroll
            for (int d4 = 0; d4 < 8; d4++) {
                float4 kv = kt[d4 * N_];
#pragma unroll
                for (int ii = 0; ii < 8; ii++) {
                    float4 q = sB4[ii][half * 8 + d4];
                    acc[ii] += q.x * kv.x + q.y * kv.y + q.z * kv.z + q.w * kv.w;
                }
            }
#pragma unroll
            for (int ii = 0; ii < 8; ii++) parts[half][ii][j] = acc[ii];
            __syncthreads();
            if (tid < 256) {
                float ck = g_colK[(p * H_ + h) * N_ + j];
                float cd = g_cdiffs[l * H_ + h];
                const float* dptr = g_diffs + (l * H_ + h) * (N_ * N_);
#pragma unroll
                for (int ii = 0; ii < 8; ii++) {
                    int pr = (i0 + ii) * N_ + j;
                    float dv = g_act[pr] ? dptr[pr] : cd;
                    parts[0][ii][j] = parts[0][ii][j] + parts[1][ii][j] + ck + dv;
                }
            }
            __syncthreads();
            int w = tid >> 5, lane = tid & 31;
            if (w < 8) {                          // warp w owns row i0+w
                float a[8];
#pragma unroll
                for (int k = 0; k < 8; k++) a[k] = parts[0][w][k * 32 + lane];
                float mx = a[0];
#pragma unroll
                for (int k = 1; k < 8; k++) mx = fmaxf(mx, a[k]);
#pragma unroll
                for (int s = 16; s > 0; s >>= 1) mx = fmaxf(mx, __shfl_xor_sync(0xFFFFFFFFu, mx, s));
                float e[8], ssum = 0.f;
#pragma unroll
                for (int k = 0; k < 8; k++) { e[k] = expf(a[k] - mx); ssum += e[k]; }
#pragma unroll
                for (int s = 16; s > 0; s >>= 1) ssum += __shfl_xor_sync(0xFFFFFFFFu, ssum, s);
                int i = i0 + w;
                float predPrev;
                if (l == 0) predPrev = g_pred0[i];
                else {
                    int pb2 = p ^ 1;
                    predPrev = 0.25f * (g_vals[pb2][0][i] + g_vals[pb2][1][i] +
                                        g_vals[pb2][2][i] + g_vals[pb2][3][i]);
                }
                float vs = 0.f;
#pragma unroll
                for (int k = 0; k < 8; k++) {
                    int jj = k * 32 + lane;
                    float v = (jj == i) ? predPrev : nt[jj];
                    vs += e[k] * v;
                }
#pragma unroll
                for (int s = 16; s > 0; s >>= 1) vs += __shfl_xor_sync(0xFFFFFFFFu, vs, s);
                if (lane == 0) {
                    float r = vs / ssum;
                    if (isLast) atomicAdd(&out[i], 0.25f * r);
                    else        g_vals[p][h][i] = r;
                }
            }
        } else if (!isLast) {
            // -------- A_{l+1}: update rows with layer-l LN, then layer-(l+1) GEMVs --
            int ln = l + 1, pn = ln & 1;
            float (*sq)[D_]  = (float(*)[D_])sm;
            float (*srs)[D_] = (float(*)[D_])(sm + 2048);
            float (*srq)[D_] = (float(*)[D_])(sm + 4096);
            int ab = b - 128; bool isK = ab >= 32; int r0 = (ab & 31) * 8;
            float* x = isK ? g_k : g_q;
            int rr = tid >> 6, c = tid & 63, row = r0 + rr;
            {
                float u = g_u[(isK ? 1 : 0) * N_ * D_ + row * D_ + c];
                float y = x[row * D_ + c] + mishf(u);
                srs[rr][c] = y; srq[rr][c] = y * y;
                __syncthreads();
                for (int s = 32; s > 0; s >>= 1) {
                    if (c < s) { srs[rr][c] += srs[rr][c + s]; srq[rr][c] += srq[rr][c + s]; }
                    __syncthreads();
                }
                const float* G  = (isK ? klnG : qlnG) + l * D_;
                const float* Bt = (isK ? klnB : qlnB) + l * D_;
                float mean = srs[rr][0] * (1.0f / 64.0f);
                float var  = srq[rr][0] * (1.0f / 64.0f) - mean * mean;
                float o = (y - mean) * rsqrtf(var + EPS_) * G[c] + Bt[c];
                x[row * D_ + c] = o;
                sq[rr][c] = o;
            }
            __syncthreads();
            if (!isK) {
                const float* A0 = g_At + ((ln * H_ + 0) * D_) * D_;
                const float* A1 = g_At + ((ln * H_ + 1) * D_) * D_;
                const float* A2 = g_At + ((ln * H_ + 2) * D_) * D_;
                const float* A3 = g_At + ((ln * H_ + 3) * D_) * D_;
                const float* Mq = g_M + (ln * 2 + 0) * D_ * D_;
                float b0 = 0, b1 = 0, b2 = 0, b3 = 0, au = 0;
#pragma unroll 8
                for (int d = 0; d < D_; d++) {
                    float qv = sq[rr][d];
                    b0 += qv * A0[d * D_ + c];
                    b1 += qv * A1[d * D_ + c];
                    b2 += qv * A2[d * D_ + c];
                    b3 += qv * A3[d * D_ + c];
                    au += qv * Mq[d * D_ + c];
                }
                g_B[((pn * H_ + 0) * N_ + row) * D_ + c] = b0;
                g_B[((pn * H_ + 1) * N_ + row) * D_ + c] = b1;
                g_B[((pn * H_ + 2) * N_ + row) * D_ + c] = b2;
                g_B[((pn * H_ + 3) * N_ + row) * D_ + c] = b3;
                g_u[0 * N_ * D_ + row * D_ + c] = au + g_v[(ln * 2 + 0) * D_ + c];
            } else {
                const float* Mk = g_M + (ln * 2 + 1) * D_ * D_;
                float au = 0;
#pragma unroll 8
                for (int d = 0; d < D_; d++) au += sq[rr][d] * Mk[d * D_ + c];
                g_u[1 * N_ * D_ + row * D_ + c] = au + g_v[(ln * 2 + 1) * D_ + c];
                ((float*)g_kT4)[((pn * 16 + (c >> 2)) * N_ + row) * 4 + (c & 3)] = sq[rr][c];
                if (c < 4) {
                    const float* bt = g_bt + (ln * H_ + c) * D_;
                    float s = 0.f;
#pragma unroll 8
                    for (int d = 0; d < D_; d++) s += sq[rr][d] * bt[d];
                    g_colK[(pn * H_ + c) * N_ + row] = s;
                }
            }
        }
        if (isLast) {
            if (b == 0 && tid == 0) g_pairCount = 0;   // prep next replay
        } else {
            gridBar();
        }
    }
}

// ---------------- launch ----------------
extern "C" void kernel_launch(void* const* d_in, const int* in_sizes, int n_in,
                              void* d_out, int out_size) {
    const float* X     = (const float*)d_in[0];
    const float* E     = (const float*)d_in[1];
    const float* nt    = (const float*)d_in[2];
    const float* embW  = (const float*)d_in[3];
    const float* embB  = (const float*)d_in[4];
    const float* boutW = (const float*)d_in[5];
    const float* boutB = (const float*)d_in[6];
    const float* qpW   = (const float*)d_in[7];
    const float* qpB   = (const float*)d_in[8];
    const float* kpW   = (const float*)d_in[9];
    const float* kpB   = (const float*)d_in[10];
    const float* qoW   = (const float*)d_in[11];
    const float* qoB   = (const float*)d_in[12];
    const float* koW   = (const float*)d_in[13];
    const float* koB   = (const float*)d_in[14];
    const float* bpW   = (const float*)d_in[15];
    const float* bpB   = (const float*)d_in[16];
    const float* bowW  = (const float*)d_in[17];
    const float* bowB  = (const float*)d_in[18];
    const float* qlnG  = (const float*)d_in[19];
    const float* qlnB  = (const float*)d_in[20];
    const float* klnG  = (const float*)d_in[21];
    const float* klnB  = (const float*)d_in[22];
    float* out = (float*)d_out;

    k_mega<<<G_, 512>>>(X, E, nt, embW, embB, boutW, boutB,
                        qpW, qpB, kpW, kpB, qoW, qoB, koW, koB,
                        bpW, bpB, bowW, bowB, qlnG, qlnB, klnG, klnB, out);
}

// round 12
// speedup vs baseline: 3.0038x; 1.2241x over previous
#include <cuda_runtime.h>
#include <math.h>

#define N_   256
#define FB_  256
#define D_   64
#define H_   4
#define DH_  128
#define HD_  512
#define BD_  128
#define HBD_ 512
#define AK_  100
#define L_   4
#define EPS_ 1e-5f
#define G_   192   // persistent grid; all blocks co-resident (2/SM guaranteed)

// ---------------- scratch (device globals; zero-init, no allocations) ----------------
__device__ float g_d[N_ * N_];
__device__ unsigned char g_act[N_ * N_];
__device__ int   g_pairCount;
__device__ int   g_pairList[N_ * N_];
__device__ float g_diffs[L_ * H_ * N_ * N_];
__device__ float g_cdiffs[L_ * H_];
__device__ float g_q[N_ * D_];
__device__ float g_k[N_ * D_];
__device__ float g_pred0[N_];
__device__ float g_At[L_ * H_ * D_ * D_];      // [l][h][d][c] = Wq_h Wk_h^T / sqrt(DH)
__device__ float g_M[L_ * 2 * D_ * D_];        // [l][qk][d][c] effective update matrix
__device__ float g_v[L_ * 2 * D_];             // effective update bias
__device__ float g_bt[L_ * H_ * D_];           // [l][h][c] = Wk_h @ qpB_h / sqrt(DH)
__device__ float g_B[2 * H_ * N_ * D_];        // parity  [p][h][i][c]
__device__ float4 g_kT4[2 * 16 * N_];          // parity  [p][d4][j] (4 dh comps)
__device__ float g_colK[2 * H_ * N_];          // parity  [p][h][j]
__device__ float g_u[2 * N_ * D_];             // [qk][row][c] update pre-activation
__device__ float g_vals[2][H_][N_];
__device__ unsigned g_barArrive;
__device__ unsigned g_barGen;

__device__ __forceinline__ float mishf(float x) {
    float sp = (x > 20.f) ? x : log1pf(expf(x));
    return x * tanhf(sp);
}

__device__ __forceinline__ void gridBar() {
    __threadfence();
    __syncthreads();
    if (threadIdx.x == 0) {
        unsigned gen = __ldcg(&g_barGen);
        unsigned t = atomicAdd(&g_barArrive, 1u);
        if (t == G_ - 1) {
            g_barArrive = 0u;
            __threadfence();
            atomicExch(&g_barGen, gen + 1u);
        } else {
            while (__ldcg(&g_barGen) == gen) __nanosleep(32);
        }
    }
    __syncthreads();
    __threadfence();
}

__global__ __launch_bounds__(512, 2)
void k_mega(const float* __restrict__ X, const float* __restrict__ E,
            const float* __restrict__ nt,
            const float* __restrict__ embW, const float* __restrict__ embB,
            const float* __restrict__ boutW, const float* __restrict__ boutB,
            const float* __restrict__ qpW, const float* __restrict__ qpB,
            const float* __restrict__ kpW, const float* __restrict__ kpB,
            const float* __restrict__ qoW, const float* __restrict__ qoB,
            const float* __restrict__ koW, const float* __restrict__ koB,
            const float* __restrict__ bpW, const float* __restrict__ bpB,
            const float* __restrict__ bowW, const float* __restrict__ bowB,
            const float* __restrict__ qlnG, const float* __restrict__ qlnB,
            const float* __restrict__ klnG, const float* __restrict__ klnB,
            float* __restrict__ out) {
    __shared__ __align__(16) char sm[20608];
    int b = blockIdx.x, tid = threadIdx.x;     // 512 threads

    // ============ Phase 0: blocks 0-127: embed/pred0/dist ; 128-191: PRE ============
    if (b < 128) {
        int half = tid >> 8, t = tid & 255;
        char* hb = sm + half * 2560;
        float* sx   = (float*)hb;
        float* se   = (float*)(hb + 1024);
        float* red  = (float*)(hb + 1440);
        float* wred = (float*)(hb + 2464);
        int i = 2 * b + half;
        sx[t] = X[i * FB_ + t];
        if (t < AK_) se[t] = E[i * AK_ + t];
        if (t == 0) out[i] = 0.f;
        __syncthreads();
        // ---- distances: warp-cooperative, 16 lanes per j row (coalesced E reads) ----
        {
            int w8 = (t >> 5);                  // warp within half: 0..7
            int lane = t & 31;
            int sub = lane & 15, jh = lane >> 4;
            for (int pass = 0; pass < 16; pass++) {
                int j = pass * 16 + w8 * 2 + jh;
                float s = 0.f;
                const float* Ej = E + j * AK_;
#pragma unroll
                for (int k = sub; k < AK_; k += 16) { float d = se[k] - Ej[k]; s += d * d; }
#pragma unroll
                for (int sh = 8; sh > 0; sh >>= 1) s += __shfl_xor_sync(0xFFFFFFFFu, s, sh);
                if (sub == 0) {
                    float dd = (s > 0.f) ? sqrtf(s) : 0.f;
                    g_d[i * N_ + j] = dd;
                    // d>2 => every RBF term exp(<-127) == exactly 0.0f in fp32 (same as ref)
                    bool act = (dd <= 2.0f);
                    g_act[i * N_ + j] = act ? 1 : 0;
                    if (act) {
                        int p = atomicAdd(&g_pairCount, 1);
                        g_pairList[p] = i * N_ + j;
                    }
                }
            }
        }
        {
            int c = t & 63, part = t >> 6;
            float acc = 0.f;
            const float* wp = embW + (part * 64) * D_ + c;
#pragma unroll 16
            for (int f = 0; f < 64; f++) acc += sx[part * 64 + f] * wp[f * D_];
            red[t] = acc;
        }
        __syncthreads();
        if (t < D_) {
            float v = red[t] + red[t + 64] + red[t + 128] + red[t + 192] + embB[t];
            g_q[i * D_ + t] = v;
            g_k[i * D_ + t] = v;
        }
        float pacc = sx[t] * boutW[t];
#pragma unroll
        for (int s = 16; s > 0; s >>= 1) pacc += __shfl_xor_sync(0xFFFFFFFFu, pacc, s);
        if ((t & 31) == 0) wred[t >> 5] = pacc;
        __syncthreads();
        if (t == 0) {
            float s = 0.f;
#pragma unroll
            for (int w = 0; w < 8; w++) s += wred[w];
            g_pred0[i] = s + boutB[0];
        }
    } else {
        int bt = b - 128;
        int c = tid & 63, rg = tid >> 6;
        if (bt < 16) {
            // ---- Atilde (l,h) + col-bias b~ ----
            int l = bt >> 2, h = bt & 3;
            float (*smK)[65] = (float(*)[65])sm;
            float acc[8];
#pragma unroll
            for (int u = 0; u < 8; u++) acc[u] = 0.f;
            float bacc = 0.f;
            for (int d0 = 0; d0 < DH_; d0 += 64) {
                __syncthreads();
                for (int idx = tid; idx < 4096; idx += 512) {
                    int cc = idx >> 6, d = idx & 63;
                    smK[cc][d] = kpW[l * (D_ * HD_) + cc * HD_ + h * DH_ + d0 + d];
                }
                __syncthreads();
                const float* qp = qpW + l * (D_ * HD_) + h * DH_ + d0;
                const float* qb = qpB + l * HD_ + h * DH_ + d0;
#pragma unroll 4
                for (int d = 0; d < 64; d++) {
                    float w = smK[c][d];
#pragma unroll
                    for (int u = 0; u < 8; u++) acc[u] += qp[(rg * 8 + u) * HD_ + d] * w;
                    if (rg == 0) bacc += w * qb[d];
                }
            }
            const float s = 0.08838834764831843f;  // 1/sqrt(128)
#pragma unroll
            for (int u = 0; u < 8; u++)
                g_At[((l * H_ + h) * D_ + rg * 8 + u) * D_ + c] = acc[u] * s;
            if (rg == 0) g_bt[(l * H_ + h) * D_ + c] = bacc * s;
        } else if (bt < 24) {
            // ---- M (l,qk) + v ----
            int l = (bt - 16) >> 1, qk = (bt - 16) & 1;
            const float* Wp  = (qk ? kpW : qpW) + l * D_ * HD_;
            const float* WpB = (qk ? kpB : qpB) + l * HD_;
            const float* Wo  = (qk ? koW : qoW) + l * HD_ * D_;
            const float* WoB = (qk ? koB : qoB) + l * D_;
            float (*smP)[65] = (float(*)[65])sm;
            float acc[8];
#pragma unroll
            for (int u = 0; u < 8; u++) acc[u] = 0.f;
            float vacc = 0.f;
            for (int s0 = 0; s0 < HD_; s0 += 64) {
                __syncthreads();
                for (int idx = tid; idx < 4096; idx += 512) {
                    int dd = idx >> 6, ss = idx & 63;
                    smP[dd][ss] = Wp[dd * HD_ + s0 + ss];
                }
                __syncthreads();
#pragma unroll 4
                for (int ss = 0; ss < 64; ss++) {
                    int s = s0 + ss;
                    int m = ((s & 127) << 2) | (s >> 7);   // inverse head/dh permutation
                    float w = Wo[m * D_ + c];
#pragma unroll
                    for (int u = 0; u < 8; u++) acc[u] += smP[rg * 8 + u][ss] * w;
                    if (rg == 0) vacc += WpB[s] * w;
                }
            }
#pragma unroll
            for (int u = 0; u < 8; u++)
                g_M[((l * 2 + qk) * D_ + rg * 8 + u) * D_ + c] = acc[u];
            if (rg == 0) g_v[(l * 2 + qk) * D_ + c] = vacc + WoB[c];
        }
    }
    gridBar();

    // ===== Phase 1: blocks 0-127: bias pipeline (4 pairs/chunk) ; 128-191: A_0 ======
    if (b < 128) {
        float (*beta)[BD_]  = (float(*)[BD_])sm;                 // 2 KB
        float (*sb)[HBD_]   = (float(*)[HBD_])(sm + 2048);       // 8 KB
        float (*parts)[512] = (float(*)[512])(sm + 10240);       // 8 KB
        int*   svp          = (int*)(sm + 18432);
        float* sd           = (float*)(sm + 18464);
        int total = g_pairCount + 1;
        int nChunks = (total + 3) >> 2;
        for (int ch = b; ch < nChunks; ch += 128) {
            int pbase = ch << 2;
            int np = total - pbase; if (np > 4) np = 4;
            if (tid < 4) {
                int vp = pbase + tid;
                if (tid < np) {
                    if (vp == 0) { svp[tid] = -1; sd[tid] = 0.f; }
                    else { int pr = g_pairList[vp - 1]; svp[tid] = pr; sd[tid] = g_d[pr]; }
                } else { svp[tid] = -2; sd[tid] = 0.f; }
            }
            __syncthreads();
            {
                int p = tid >> 7, c = tid & 127;
                float ddv = sd[p] - (float)c * (1.0f / 127.0f);
                beta[p][c] = (p < np && svp[p] >= 0) ? expf(-127.0f * ddv * ddv) : 0.f;
            }
            __syncthreads();
            for (int l = 0; l < L_; l++) {
                // GEMV1: 512 output cols, 4 pairs each
                const float* W = bpW + l * BD_ * HBD_;
                float acc0 = 0.f, acc1 = 0.f, acc2 = 0.f, acc3 = 0.f;
#pragma unroll 8
                for (int c = 0; c < BD_; c++) {
                    float w = W[c * HBD_ + tid];
                    acc0 += beta[0][c] * w;
                    acc1 += beta[1][c] * w;
                    acc2 += beta[2][c] * w;
                    acc3 += beta[3][c] * w;
                }
                float bb = bpB[l * HBD_ + tid];
                sb[0][tid] = acc0 + bb;
                sb[1][tid] = acc1 + bb;
                sb[2][tid] = acc2 + bb;
                sb[3][tid] = acc3 + bb;
                __syncthreads();
                // norms (16 threads) run alongside GEMV2 start
                if (tid < 16) {
                    int p = tid >> 2, h = tid & 3;
                    if (p < np && svp[p] != -2) {
                        float s = 0.f;
#pragma unroll 8
                        for (int bd = 0; bd < BD_; bd++) { float v = sb[p][h * BD_ + bd]; s += v * v; }
                        float r = sqrtf(s);
                        if (svp[p] == -1) g_cdiffs[l * H_ + h] = r;
                        else              g_diffs[(l * H_ + h) * (N_ * N_) + svp[p]] = r;
                    }
                }
                if (l < L_ - 1) {
                    // GEMV2 split: os = tid>>7 covers o in [os*128, os*128+128)
                    int c = tid & 127, os = tid >> 7;
                    const float* W2 = bowW + l * HBD_ * BD_;
                    float a0 = 0.f, a1 = 0.f, a2 = 0.f, a3 = 0.f;
                    int o0 = os * 128;
#pragma unroll 8
                    for (int oo = 0; oo < 128; oo++) {
                        int o = o0 + oo;
                        float w = W2[o * BD_ + c];
                        a0 += sb[0][o] * w;
                        a1 += sb[1][o] * w;
                        a2 += sb[2][o] * w;
                        a3 += sb[3][o] * w;
                    }
                    parts[os][0 * BD_ + c] = a0;
                    parts[os][1 * BD_ + c] = a1;
                    parts[os][2 * BD_ + c] = a2;
                    parts[os][3 * BD_ + c] = a3;
                    __syncthreads();
                    int p = tid >> 7, cc = tid & 127;
                    float v = parts[0][p * BD_ + cc] + parts[1][p * BD_ + cc]
                            + parts[2][p * BD_ + cc] + parts[3][p * BD_ + cc]
                            + bowB[l * BD_ + cc];
                    beta[p][cc] = mishf(v);
                }
                __syncthreads();
            }
            __syncthreads();
        }
    } else {
        // -------- A_0: build B/u/colK/kT for layer 0 (parity 0) --------
        float (*sq)[D_] = (float(*)[D_])sm;
        int ab = b - 128; bool isK = ab >= 32; int r0 = (ab & 31) * 8;
        const float* x = isK ? g_k : g_q;
        int rr = tid >> 6, c = tid & 63, row = r0 + rr;
        sq[rr][c] = x[row * D_ + c];
        __syncthreads();
        const int l = 0, p = 0;
        if (!isK) {
            const float* A0 = g_At + ((l * H_ + 0) * D_) * D_;
            const float* A1 = g_At + ((l * H_ + 1) * D_) * D_;
            const float* A2 = g_At + ((l * H_ + 2) * D_) * D_;
            const float* A3 = g_At + ((l * H_ + 3) * D_) * D_;
            const float* Mq = g_M + (l * 2 + 0) * D_ * D_;
            float b0 = 0, b1 = 0, b2 = 0, b3 = 0, au = 0;
#pragma unroll 8
            for (int d = 0; d < D_; d++) {
                float qv = sq[rr][d];
                b0 += qv * A0[d * D_ + c];
                b1 += qv * A1[d * D_ + c];
                b2 += qv * A2[d * D_ + c];
                b3 += qv * A3[d * D_ + c];
                au += qv * Mq[d * D_ + c];
            }
            g_B[((p * H_ + 0) * N_ + row) * D_ + c] = b0;
            g_B[((p * H_ + 1) * N_ + row) * D_ + c] = b1;
            g_B[((p * H_ + 2) * N_ + row) * D_ + c] = b2;
            g_B[((p * H_ + 3) * N_ + row) * D_ + c] = b3;
            g_u[0 * N_ * D_ + row * D_ + c] = au + g_v[(l * 2 + 0) * D_ + c];
        } else {
            const float* Mk = g_M + (l * 2 + 1) * D_ * D_;
            float au = 0;
#pragma unroll 8
            for (int d = 0; d < D_; d++) au += sq[rr][d] * Mk[d * D_ + c];
            g_u[1 * N_ * D_ + row * D_ + c] = au + g_v[(l * 2 + 1) * D_ + c];
            ((float*)g_kT4)[((p * 16 + (c >> 2)) * N_ + row) * 4 + (c & 3)] = sq[rr][c];
            if (c < 4) {
                const float* bt = g_bt + (l * H_ + c) * D_;
                float s = 0.f;
#pragma unroll 8
                for (int d = 0; d < D_; d++) s += sq[rr][d] * bt[d];
                g_colK[(p * H_ + c) * N_ + row] = s;
            }
        }
    }
    gridBar();

    // ============ layer loop: attn_l (0-127) || A_{l+1} (128-191) ============
    for (int l = 0; l < L_; l++) {
        int isLast = (l == L_ - 1);
        int p = l & 1;
        if (b < 128) {
            // -------- attention (head h, 8-row tile), depth 64 split over halves ----
            float (*sB)[D_]   = (float(*)[D_])sm;                     // 2 KB
            float4 (*sB4)[16] = (float4(*)[16])sm;
            float (*parts)[8][256] = (float(*)[8][256])(sm + 2048);   // 16 KB
            int h = b & 3, i0 = (b >> 2) * 8;
            sB[tid >> 6][tid & 63] =
                g_B[((p * H_ + h) * N_ + i0 + (tid >> 6)) * D_ + (tid & 63)];
            __syncthreads();
            int half = tid >> 8, j = tid & 255;
            float acc[8];
#pragma unroll
            for (int ii = 0; ii < 8; ii++) acc[ii] = 0.f;
            const float4* kt = g_kT4 + (p * 16 + half * 8) * N_ + j;
#pragma unroll
            for (int d4 = 0; d4 < 8; d4++) {
                float4 kv = kt[d4 * N_];
#pragma unroll
                for (int ii = 0; ii < 8; ii++) {
                    float4 q = sB4[ii][half * 8 + d4];
                    acc[ii] += q.x * kv.x + q.y * kv.y + q.z * kv.z + q.w * kv.w;
                }
            }
#pragma unroll
            for (int ii = 0; ii < 8; ii++) parts[half][ii][j] = acc[ii];
            __syncthreads();
            if (tid < 256) {
                float ck = g_colK[(p * H_ + h) * N_ + j];
                float cd = g_cdiffs[l * H_ + h];
                const float* dptr = g_diffs + (l * H_ + h) * (N_ * N_);
#pragma unroll
                for (int ii = 0; ii < 8; ii++) {
                    int pr = (i0 + ii) * N_ + j;
                    float dv = g_act[pr] ? dptr[pr] : cd;
                    parts[0][ii][j] = parts[0][ii][j] + parts[1][ii][j] + ck + dv;
                }
            }
            __syncthreads();
            int w = tid >> 5, lane = tid & 31;
            if (w < 8) {                          // warp w owns row i0+w
                float a[8];
#pragma unroll
                for (int k = 0; k < 8; k++) a[k] = parts[0][w][k * 32 + lane];
                float mx = a[0];
#pragma unroll
                for (int k = 1; k < 8; k++) mx = fmaxf(mx, a[k]);
#pragma unroll
                for (int s = 16; s > 0; s >>= 1) mx = fmaxf(mx, __shfl_xor_sync(0xFFFFFFFFu, mx, s));
                float e[8], ssum = 0.f;
#pragma unroll
                for (int k = 0; k < 8; k++) { e[k] = expf(a[k] - mx); ssum += e[k]; }
#pragma unroll
                for (int s = 16; s > 0; s >>= 1) ssum += __shfl_xor_sync(0xFFFFFFFFu, ssum, s);
                int i = i0 + w;
                float predPrev;
                if (l == 0) predPrev = g_pred0[i];
                else {
                    int pb2 = p ^ 1;
                    predPrev = 0.25f * (g_vals[pb2][0][i] + g_vals[pb2][1][i] +
                                        g_vals[pb2][2][i] + g_vals[pb2][3][i]);
                }
                float vs = 0.f;
#pragma unroll
                for (int k = 0; k < 8; k++) {
                    int jj = k * 32 + lane;
                    float v = (jj == i) ? predPrev : nt[jj];
                    vs += e[k] * v;
                }
#pragma unroll
                for (int s = 16; s > 0; s >>= 1) vs += __shfl_xor_sync(0xFFFFFFFFu, vs, s);
                if (lane == 0) {
                    float r = vs / ssum;
                    if (isLast) atomicAdd(&out[i], 0.25f * r);
                    else        g_vals[p][h][i] = r;
                }
            }
        } else if (!isLast) {
            // -------- A_{l+1}: update rows with layer-l LN, then layer-(l+1) GEMVs --
            int ln = l + 1, pn = ln & 1;
            float (*sq)[D_]  = (float(*)[D_])sm;
            float (*srs)[D_] = (float(*)[D_])(sm + 2048);
            float (*srq)[D_] = (float(*)[D_])(sm + 4096);
            int ab = b - 128; bool isK = ab >= 32; int r0 = (ab & 31) * 8;
            float* x = isK ? g_k : g_q;
            int rr = tid >> 6, c = tid & 63, row = r0 + rr;
            {
                float u = g_u[(isK ? 1 : 0) * N_ * D_ + row * D_ + c];
                float y = x[row * D_ + c] + mishf(u);
                srs[rr][c] = y; srq[rr][c] = y * y;
                __syncthreads();
                for (int s = 32; s > 0; s >>= 1) {
                    if (c < s) { srs[rr][c] += srs[rr][c + s]; srq[rr][c] += srq[rr][c + s]; }
                    __syncthreads();
                }
                const float* G  = (isK ? klnG : qlnG) + l * D_;
                const float* Bt = (isK ? klnB : qlnB) + l * D_;
                float mean = srs[rr][0] * (1.0f / 64.0f);
                float var  = srq[rr][0] * (1.0f / 64.0f) - mean * mean;
                float o = (y - mean) * rsqrtf(var + EPS_) * G[c] + Bt[c];
                x[row * D_ + c] = o;
                sq[rr][c] = o;
            }
            __syncthreads();
            if (!isK) {
                const float* A0 = g_At + ((ln * H_ + 0) * D_) * D_;
                const float* A1 = g_At + ((ln * H_ + 1) * D_) * D_;
                const float* A2 = g_At + ((ln * H_ + 2) * D_) * D_;
                const float* A3 = g_At + ((ln * H_ + 3) * D_) * D_;
                const float* Mq = g_M + (ln * 2 + 0) * D_ * D_;
                float b0 = 0, b1 = 0, b2 = 0, b3 = 0, au = 0;
#pragma unroll 8
                for (int d = 0; d < D_; d++) {
                    float qv = sq[rr][d];
                    b0 += qv * A0[d * D_ + c];
                    b1 += qv * A1[d * D_ + c];
                    b2 += qv * A2[d * D_ + c];
                    b3 += qv * A3[d * D_ + c];
                    au += qv * Mq[d * D_ + c];
                }
                g_B[((pn * H_ + 0) * N_ + row) * D_ + c] = b0;
                g_B[((pn * H_ + 1) * N_ + row) * D_ + c] = b1;
                g_B[((pn * H_ + 2) * N_ + row) * D_ + c] = b2;
                g_B[((pn * H_ + 3) * N_ + row) * D_ + c] = b3;
                g_u[0 * N_ * D_ + row * D_ + c] = au + g_v[(ln * 2 + 0) * D_ + c];
            } else {
                const float* Mk = g_M + (ln * 2 + 1) * D_ * D_;
                float au = 0;
#pragma unroll 8
                for (int d = 0; d < D_; d++) au += sq[rr][d] * Mk[d * D_ + c];
                g_u[1 * N_ * D_ + row * D_ + c] = au + g_v[(ln * 2 + 1) * D_ + c];
                ((float*)g_kT4)[((pn * 16 + (c >> 2)) * N_ + row) * 4 + (c & 3)] = sq[rr][c];
                if (c < 4) {
                    const float* bt = g_bt + (ln * H_ + c) * D_;
                    float s = 0.f;
#pragma unroll 8
                    for (int d = 0; d < D_; d++) s += sq[rr][d] * bt[d];
                    g_colK[(pn * H_ + c) * N_ + row] = s;
                }
            }
        }
        if (isLast) {
            if (b == 0 && tid == 0) g_pairCount = 0;   // prep next replay
        } else {
            gridBar();
        }
    }
}

// ---------------- launch ----------------
extern "C" void kernel_launch(void* const* d_in, const int* in_sizes, int n_in,
                              void* d_out, int out_size) {
    const float* X     = (const float*)d_in[0];
    const float* E     = (const float*)d_in[1];
    const float* nt    = (const float*)d_in[2];
    const float* embW  = (const float*)d_in[3];
    const float* embB  = (const float*)d_in[4];
    const float* boutW = (const float*)d_in[5];
    const float* boutB = (const float*)d_in[6];
    const float* qpW   = (const float*)d_in[7];
    const float* qpB   = (const float*)d_in[8];
    const float* kpW   = (const float*)d_in[9];
    const float* kpB   = (const float*)d_in[10];
    const float* qoW   = (const float*)d_in[11];
    const float* qoB   = (const float*)d_in[12];
    const float* koW   = (const float*)d_in[13];
    const float* koB   = (const float*)d_in[14];
    const float* bpW   = (const float*)d_in[15];
    const float* bpB   = (const float*)d_in[16];
    const float* bowW  = (const float*)d_in[17];
    const float* bowB  = (const float*)d_in[18];
    const float* qlnG  = (const float*)d_in[19];
    const float* qlnB  = (const float*)d_in[20];
    const float* klnG  = (const float*)d_in[21];
    const float* klnB  = (const float*)d_in[22];
    float* out = (float*)d_out;

    k_mega<<<G_, 512>>>(X, E, nt, embW, embB, boutW, boutB,
                        qpW, qpB, kpW, kpB, qoW, qoB, koW, koB,
                        bpW, bpB, bowW, bowB, qlnG, qlnB, klnG, klnB, out);
}

// round 13
// speedup vs baseline: 3.4749x; 1.1569x over previous
#include <cuda_runtime.h>
#include <math.h>

#define N_   256
#define FB_  256
#define D_   64
#define H_   4
#define DH_  128
#define HD_  512
#define BD_  128
#define HBD_ 512
#define AK_  100
#define L_   4
#define EPS_ 1e-5f
#define G_   192   // persistent grid; all blocks co-resident (2/SM guaranteed)

// ---------------- scratch (device globals; zero-init, no allocations) ----------------
__device__ float g_d[N_ * N_];
__device__ unsigned char g_act[N_ * N_];
__device__ int   g_pairCount;
__device__ int   g_pairList[N_ * N_];
__device__ float g_diffs[L_ * H_ * N_ * N_];
__device__ float g_cdiffs[L_ * H_];
__device__ float g_q[N_ * D_];
__device__ float g_k[N_ * D_];
__device__ float g_pred0[N_];
__device__ float g_At[L_ * H_ * D_ * D_];      // [l][h][d][c] = Wq_h Wk_h^T / sqrt(DH)
__device__ float g_M[L_ * 2 * D_ * D_];        // [l][qk][d][c] effective update matrix
__device__ float g_v[L_ * 2 * D_];             // effective update bias
__device__ float g_bt[L_ * H_ * D_];           // [l][h][c] = Wk_h @ kp-side bias / sqrt(DH)
__device__ float g_B[L_ * H_ * N_ * D_];       // [l][h][i][c]
__device__ float4 g_kT4[L_ * 16 * N_];         // [l][d4][j]
__device__ float g_colK[L_ * H_ * N_];         // [l][h][j]
__device__ float g_base[L_ * H_ * N_];         // attention affine constants
__device__ float g_w[L_ * H_ * N_];
__device__ unsigned g_barArrive;
__device__ unsigned g_barGen;

__device__ __forceinline__ float mishf(float x) {
    float sp = (x > 20.f) ? x : log1pf(expf(x));
    return x * tanhf(sp);
}

__device__ __forceinline__ void gridBar() {
    __threadfence();
    __syncthreads();
    if (threadIdx.x == 0) {
        unsigned gen = __ldcg(&g_barGen);
        unsigned t = atomicAdd(&g_barArrive, 1u);
        if (t == G_ - 1) {
            g_barArrive = 0u;
            __threadfence();
            atomicExch(&g_barGen, gen + 1u);
        } else {
            while (__ldcg(&g_barGen) == gen) __nanosleep(32);
        }
    }
    __syncthreads();
    __threadfence();
}

__global__ __launch_bounds__(512, 2)
void k_mega(const float* __restrict__ X, const float* __restrict__ E,
            const float* __restrict__ nt,
            const float* __restrict__ embW, const float* __restrict__ embB,
            const float* __restrict__ boutW, const float* __restrict__ boutB,
            const float* __restrict__ qpW, const float* __restrict__ qpB,
            const float* __restrict__ kpW, const float* __restrict__ kpB,
            const float* __restrict__ qoW, const float* __restrict__ qoB,
            const float* __restrict__ koW, const float* __restrict__ koB,
            const float* __restrict__ bpW, const float* __restrict__ bpB,
            const float* __restrict__ bowW, const float* __restrict__ bowB,
            const float* __restrict__ qlnG, const float* __restrict__ qlnB,
            const float* __restrict__ klnG, const float* __restrict__ klnB,
            float* __restrict__ out) {
    __shared__ __align__(16) char sm[20608];
    int b = blockIdx.x, tid = threadIdx.x;     // 512 threads

    // ============ Phase 0: blocks 0-127: embed/pred0/dist ; 128-191: PRE ============
    if (b < 128) {
        int half = tid >> 8, t = tid & 255;
        char* hb = sm + half * 2560;
        float* sx   = (float*)hb;
        float* se   = (float*)(hb + 1024);
        float* red  = (float*)(hb + 1440);
        float* wred = (float*)(hb + 2464);
        int i = 2 * b + half;
        sx[t] = X[i * FB_ + t];
        if (t < AK_) se[t] = E[i * AK_ + t];
        __syncthreads();
        // ---- distances: warp-cooperative, 16 lanes per j row (coalesced E reads) ----
        {
            int w8 = (t >> 5);
            int lane = t & 31;
            int sub = lane & 15, jh = lane >> 4;
            for (int pass = 0; pass < 16; pass++) {
                int j = pass * 16 + w8 * 2 + jh;
                float s = 0.f;
                const float* Ej = E + j * AK_;
#pragma unroll
                for (int k = sub; k < AK_; k += 16) { float d = se[k] - Ej[k]; s += d * d; }
#pragma unroll
                for (int sh = 8; sh > 0; sh >>= 1) s += __shfl_xor_sync(0xFFFFFFFFu, s, sh);
                if (sub == 0) {
                    float dd = (s > 0.f) ? sqrtf(s) : 0.f;
                    g_d[i * N_ + j] = dd;
                    // d>2 => every RBF term exp(<-127) == exactly 0.0f in fp32 (same as ref)
                    bool act = (dd <= 2.0f);
                    g_act[i * N_ + j] = act ? 1 : 0;
                    if (act) {
                        int p = atomicAdd(&g_pairCount, 1);
                        g_pairList[p] = i * N_ + j;
                    }
                }
            }
        }
        {
            int c = t & 63, part = t >> 6;
            float acc = 0.f;
            const float* wp = embW + (part * 64) * D_ + c;
#pragma unroll 16
            for (int f = 0; f < 64; f++) acc += sx[part * 64 + f] * wp[f * D_];
            red[t] = acc;
        }
        __syncthreads();
        if (t < D_) {
            float v = red[t] + red[t + 64] + red[t + 128] + red[t + 192] + embB[t];
            g_q[i * D_ + t] = v;
            g_k[i * D_ + t] = v;
        }
        float pacc = sx[t] * boutW[t];
#pragma unroll
        for (int s = 16; s > 0; s >>= 1) pacc += __shfl_xor_sync(0xFFFFFFFFu, pacc, s);
        if ((t & 31) == 0) wred[t >> 5] = pacc;
        __syncthreads();
        if (t == 0) {
            float s = 0.f;
#pragma unroll
            for (int w = 0; w < 8; w++) s += wred[w];
            g_pred0[i] = s + boutB[0];
        }
    } else {
        int bt = b - 128;
        int c = tid & 63, rg = tid >> 6;
        if (bt < 16) {
            // ---- Atilde (l,h) + col-bias b~ ----
            int l = bt >> 2, h = bt & 3;
            float (*smK)[65] = (float(*)[65])sm;
            float acc[8];
#pragma unroll
            for (int u = 0; u < 8; u++) acc[u] = 0.f;
            float bacc = 0.f;
            for (int d0 = 0; d0 < DH_; d0 += 64) {
                __syncthreads();
                for (int idx = tid; idx < 4096; idx += 512) {
                    int cc = idx >> 6, d = idx & 63;
                    smK[cc][d] = kpW[l * (D_ * HD_) + cc * HD_ + h * DH_ + d0 + d];
                }
                __syncthreads();
                const float* qp = qpW + l * (D_ * HD_) + h * DH_ + d0;
                const float* qb = qpB + l * HD_ + h * DH_ + d0;
#pragma unroll 4
                for (int d = 0; d < 64; d++) {
                    float w = smK[c][d];
#pragma unroll
                    for (int u = 0; u < 8; u++) acc[u] += qp[(rg * 8 + u) * HD_ + d] * w;
                    if (rg == 0) bacc += w * qb[d];
                }
            }
            const float s = 0.08838834764831843f;  // 1/sqrt(128)
#pragma unroll
            for (int u = 0; u < 8; u++)
                g_At[((l * H_ + h) * D_ + rg * 8 + u) * D_ + c] = acc[u] * s;
            if (rg == 0) g_bt[(l * H_ + h) * D_ + c] = bacc * s;
        } else if (bt < 24) {
            // ---- M (l,qk) + v ----
            int l = (bt - 16) >> 1, qk = (bt - 16) & 1;
            const float* Wp  = (qk ? kpW : qpW) + l * D_ * HD_;
            const float* WpB = (qk ? kpB : qpB) + l * HD_;
            const float* Wo  = (qk ? koW : qoW) + l * HD_ * D_;
            const float* WoB = (qk ? koB : qoB) + l * D_;
            float (*smP)[65] = (float(*)[65])sm;
            float acc[8];
#pragma unroll
            for (int u = 0; u < 8; u++) acc[u] = 0.f;
            float vacc = 0.f;
            for (int s0 = 0; s0 < HD_; s0 += 64) {
                __syncthreads();
                for (int idx = tid; idx < 4096; idx += 512) {
                    int dd = idx >> 6, ss = idx & 63;
                    smP[dd][ss] = Wp[dd * HD_ + s0 + ss];
                }
                __syncthreads();
#pragma unroll 4
                for (int ss = 0; ss < 64; ss++) {
                    int s = s0 + ss;
                    int m = ((s & 127) << 2) | (s >> 7);   // inverse head/dh permutation
                    float w = Wo[m * D_ + c];
#pragma unroll
                    for (int u = 0; u < 8; u++) acc[u] += smP[rg * 8 + u][ss] * w;
                    if (rg == 0) vacc += WpB[s] * w;
                }
            }
#pragma unroll
            for (int u = 0; u < 8; u++)
                g_M[((l * 2 + qk) * D_ + rg * 8 + u) * D_ + c] = acc[u];
            if (rg == 0) g_v[(l * 2 + qk) * D_ + c] = vacc + WoB[c];
        }
    }
    gridBar();

    // ===== Phase 1: blocks 0-127: bias pipeline ; 128-191: full 4-layer A-chain =====
    if (b < 128) {
        float (*beta)[BD_]  = (float(*)[BD_])sm;                 // 2 KB
        float (*sb)[HBD_]   = (float(*)[HBD_])(sm + 2048);       // 8 KB
        float (*parts)[512] = (float(*)[512])(sm + 10240);       // 8 KB
        int*   svp          = (int*)(sm + 18432);
        float* sd           = (float*)(sm + 18464);
        int total = g_pairCount + 1;
        int nChunks = (total + 3) >> 2;
        for (int ch = b; ch < nChunks; ch += 128) {
            int pbase = ch << 2;
            int np = total - pbase; if (np > 4) np = 4;
            if (tid < 4) {
                int vp = pbase + tid;
                if (tid < np) {
                    if (vp == 0) { svp[tid] = -1; sd[tid] = 0.f; }
                    else { int pr = g_pairList[vp - 1]; svp[tid] = pr; sd[tid] = g_d[pr]; }
                } else { svp[tid] = -2; sd[tid] = 0.f; }
            }
            __syncthreads();
            {
                int p = tid >> 7, c = tid & 127;
                float ddv = sd[p] - (float)c * (1.0f / 127.0f);
                beta[p][c] = (p < np && svp[p] >= 0) ? expf(-127.0f * ddv * ddv) : 0.f;
            }
            __syncthreads();
            for (int l = 0; l < L_; l++) {
                const float* W = bpW + l * BD_ * HBD_;
                float acc0 = 0.f, acc1 = 0.f, acc2 = 0.f, acc3 = 0.f;
#pragma unroll 16
                for (int c = 0; c < BD_; c++) {
                    float w = W[c * HBD_ + tid];
                    acc0 += beta[0][c] * w;
                    acc1 += beta[1][c] * w;
                    acc2 += beta[2][c] * w;
                    acc3 += beta[3][c] * w;
                }
                float bb = bpB[l * HBD_ + tid];
                sb[0][tid] = acc0 + bb;
                sb[1][tid] = acc1 + bb;
                sb[2][tid] = acc2 + bb;
                sb[3][tid] = acc3 + bb;
                __syncthreads();
                if (tid < 16) {
                    int p = tid >> 2, h = tid & 3;
                    if (p < np && svp[p] != -2) {
                        float s = 0.f;
#pragma unroll 8
                        for (int bd = 0; bd < BD_; bd++) { float v = sb[p][h * BD_ + bd]; s += v * v; }
                        float r = sqrtf(s);
                        if (svp[p] == -1) g_cdiffs[l * H_ + h] = r;
                        else              g_diffs[(l * H_ + h) * (N_ * N_) + svp[p]] = r;
                    }
                }
                if (l < L_ - 1) {
                    int c = tid & 127, os = tid >> 7;
                    const float* W2 = bowW + l * HBD_ * BD_;
                    float a0 = 0.f, a1 = 0.f, a2 = 0.f, a3 = 0.f;
                    int o0 = os * 128;
#pragma unroll 16
                    for (int oo = 0; oo < 128; oo++) {
                        int o = o0 + oo;
                        float w = W2[o * BD_ + c];
                        a0 += sb[0][o] * w;
                        a1 += sb[1][o] * w;
                        a2 += sb[2][o] * w;
                        a3 += sb[3][o] * w;
                    }
                    parts[os][0 * BD_ + c] = a0;
                    parts[os][1 * BD_ + c] = a1;
                    parts[os][2 * BD_ + c] = a2;
                    parts[os][3 * BD_ + c] = a3;
                    __syncthreads();
                    int p = tid >> 7, cc = tid & 127;
                    float v = parts[0][p * BD_ + cc] + parts[1][p * BD_ + cc]
                            + parts[2][p * BD_ + cc] + parts[3][p * BD_ + cc]
                            + bowB[l * BD_ + cc];
                    beta[p][cc] = mishf(v);
                }
                __syncthreads();
            }
            __syncthreads();
        }
    } else {
        // -------- A-chain: 8 rows per block, all 4 layers, row-local --------
        float (*sq)[D_]  = (float(*)[D_])sm;
        float (*srs)[D_] = (float(*)[D_])(sm + 2048);
        float (*srq)[D_] = (float(*)[D_])(sm + 4096);
        int ab = b - 128; bool isK = ab >= 32; int r0 = (ab & 31) * 8;
        int rr = tid >> 6, c = tid & 63, row = r0 + rr;
        sq[rr][c] = (isK ? g_k : g_q)[row * D_ + c];
        __syncthreads();
        for (int l = 0; l < L_; l++) {
            float au = 0.f;
            if (!isK) {
                const float* A0 = g_At + ((l * H_ + 0) * D_) * D_;
                const float* A1 = g_At + ((l * H_ + 1) * D_) * D_;
                const float* A2 = g_At + ((l * H_ + 2) * D_) * D_;
                const float* A3 = g_At + ((l * H_ + 3) * D_) * D_;
                const float* Mq = g_M + (l * 2 + 0) * D_ * D_;
                float b0 = 0, b1 = 0, b2 = 0, b3 = 0;
#pragma unroll 8
                for (int d = 0; d < D_; d++) {
                    float qv = sq[rr][d];
                    b0 += qv * A0[d * D_ + c];
                    b1 += qv * A1[d * D_ + c];
                    b2 += qv * A2[d * D_ + c];
                    b3 += qv * A3[d * D_ + c];
                    au += qv * Mq[d * D_ + c];
                }
                g_B[((l * H_ + 0) * N_ + row) * D_ + c] = b0;
                g_B[((l * H_ + 1) * N_ + row) * D_ + c] = b1;
                g_B[((l * H_ + 2) * N_ + row) * D_ + c] = b2;
                g_B[((l * H_ + 3) * N_ + row) * D_ + c] = b3;
                au += g_v[(l * 2 + 0) * D_ + c];
            } else {
                const float* Mk = g_M + (l * 2 + 1) * D_ * D_;
#pragma unroll 8
                for (int d = 0; d < D_; d++) au += sq[rr][d] * Mk[d * D_ + c];
                au += g_v[(l * 2 + 1) * D_ + c];
                ((float*)g_kT4)[((l * 16 + (c >> 2)) * N_ + row) * 4 + (c & 3)] = sq[rr][c];
                if (c < 4) {
                    const float* bt = g_bt + (l * H_ + c) * D_;
                    float s = 0.f;
#pragma unroll 8
                    for (int d = 0; d < D_; d++) s += sq[rr][d] * bt[d];
                    g_colK[(l * H_ + c) * N_ + row] = s;
                }
            }
            if (l < L_ - 1) {
                float y = sq[rr][c] + mishf(au);
                srs[rr][c] = y; srq[rr][c] = y * y;
                __syncthreads();
                for (int s = 32; s > 0; s >>= 1) {
                    if (c < s) { srs[rr][c] += srs[rr][c + s]; srq[rr][c] += srq[rr][c + s]; }
                    __syncthreads();
                }
                const float* G  = (isK ? klnG : qlnG) + l * D_;
                const float* Bt = (isK ? klnB : qlnB) + l * D_;
                float mean = srs[rr][0] * (1.0f / 64.0f);
                float var  = srq[rr][0] * (1.0f / 64.0f) - mean * mean;
                float o = (y - mean) * rsqrtf(var + EPS_) * G[c] + Bt[c];
                __syncthreads();
                sq[rr][c] = o;
                __syncthreads();
            }
        }
    }
    gridBar();

    // ====== Phase 2: 512 (l,h,tile8) softmax units, fully parallel, grid-stride =====
    {
        float (*sB)[D_]   = (float(*)[D_])sm;                     // 2 KB
        float4 (*sB4)[16] = (float4(*)[16])sm;
        float (*parts)[8][256] = (float(*)[8][256])(sm + 2048);   // 16 KB
        for (int u = b; u < 512; u += G_) {
            int l = u >> 7, h = (u >> 5) & 3, i0 = (u & 31) * 8;
            __syncthreads();
            sB[tid >> 6][tid & 63] =
                g_B[((l * H_ + h) * N_ + i0 + (tid >> 6)) * D_ + (tid & 63)];
            __syncthreads();
            int half = tid >> 8, j = tid & 255;
            float acc[8];
#pragma unroll
            for (int ii = 0; ii < 8; ii++) acc[ii] = 0.f;
            const float4* kt = g_kT4 + (l * 16 + half * 8) * N_ + j;
#pragma unroll
            for (int d4 = 0; d4 < 8; d4++) {
                float4 kv = kt[d4 * N_];
#pragma unroll
                for (int ii = 0; ii < 8; ii++) {
                    float4 q = sB4[ii][half * 8 + d4];
                    acc[ii] += q.x * kv.x + q.y * kv.y + q.z * kv.z + q.w * kv.w;
                }
            }
#pragma unroll
            for (int ii = 0; ii < 8; ii++) parts[half][ii][j] = acc[ii];
            __syncthreads();
            if (tid < 256) {
                float ck = g_colK[(l * H_ + h) * N_ + j];
                float cd = g_cdiffs[l * H_ + h];
                const float* dptr = g_diffs + (l * H_ + h) * (N_ * N_);
#pragma unroll
                for (int ii = 0; ii < 8; ii++) {
                    int pr = (i0 + ii) * N_ + j;
                    float dv = g_act[pr] ? dptr[pr] : cd;
                    parts[0][ii][j] = parts[0][ii][j] + parts[1][ii][j] + ck + dv;
                }
            }
            __syncthreads();
            int w = tid >> 5, lane = tid & 31;
            if (w < 8) {                          // warp w owns row i0+w
                int i = i0 + w;
                float a[8];
#pragma unroll
                for (int k = 0; k < 8; k++) a[k] = parts[0][w][k * 32 + lane];
                float mx = a[0];
#pragma unroll
                for (int k = 1; k < 8; k++) mx = fmaxf(mx, a[k]);
#pragma unroll
                for (int s = 16; s > 0; s >>= 1) mx = fmaxf(mx, __shfl_xor_sync(0xFFFFFFFFu, mx, s));
                float e[8], ssum = 0.f, vs = 0.f, eD = 0.f;
#pragma unroll
                for (int k = 0; k < 8; k++) {
                    e[k] = expf(a[k] - mx);
                    ssum += e[k];
                    int jj = k * 32 + lane;
                    vs += e[k] * nt[jj];
                    if (jj == i) eD = e[k];
                }
#pragma unroll
                for (int s = 16; s > 0; s >>= 1) {
                    ssum += __shfl_xor_sync(0xFFFFFFFFu, ssum, s);
                    vs   += __shfl_xor_sync(0xFFFFFFFFu, vs, s);
                    eD   += __shfl_xor_sync(0xFFFFFFFFu, eD, s);
                }
                if (lane == 0) {
                    float inv = 1.0f / ssum;
                    g_base[(l * H_ + h) * N_ + i] = (vs - eD * nt[i]) * inv;
                    g_w[(l * H_ + h) * N_ + i]    = eD * inv;
                }
            }
        }
    }
    gridBar();

    // ====== Phase 3: scalar affine fold over layers -> out ======
    if (b == 0) {
        if (tid < 256) {
            int i = tid;
            float p = g_pred0[i];
#pragma unroll
            for (int l = 0; l < L_; l++) {
                float s = 0.f;
#pragma unroll
                for (int h = 0; h < H_; h++)
                    s += g_base[(l * H_ + h) * N_ + i] + g_w[(l * H_ + h) * N_ + i] * p;
                p = 0.25f * s;
            }
            out[i] = p;
        }
        if (tid == 256) g_pairCount = 0;   // prep next replay
    }
}

// ---------------- launch ----------------
extern "C" void kernel_launch(void* const* d_in, const int* in_sizes, int n_in,
                              void* d_out, int out_size) {
    const float* X     = (const float*)d_in[0];
    const float* E     = (const float*)d_in[1];
    const float* nt    = (const float*)d_in[2];
    const float* embW  = (const float*)d_in[3];
    const float* embB  = (const float*)d_in[4];
    const float* boutW = (const float*)d_in[5];
    const float* boutB = (const float*)d_in[6];
    const float* qpW   = (const float*)d_in[7];
    const float* qpB   = (const float*)d_in[8];
    const float* kpW   = (const float*)d_in[9];
    const float* kpB   = (const float*)d_in[10];
    const float* qoW   = (const float*)d_in[11];
    const float* qoB   = (const float*)d_in[12];
    const float* koW   = (const float*)d_in[13];
    const float* koB   = (const float*)d_in[14];
    const float* bpW   = (const float*)d_in[15];
    const float* bpB   = (const float*)d_in[16];
    const float* bowW  = (const float*)d_in[17];
    const float* bowB  = (const float*)d_in[18];
    const float* qlnG  = (const float*)d_in[19];
    const float* qlnB  = (const float*)d_in[20];
    const float* klnG  = (const float*)d_in[21];
    const float* klnB  = (const float*)d_in[22];
    float* out = (float*)d_out;

    k_mega<<<G_, 512>>>(X, E, nt, embW, embB, boutW, boutB,
                        qpW, qpB, kpW, kpB, qoW, qoB, koW, koB,
                        bpW, bpB, bowW, bowB, qlnG, qlnB, klnG, klnB, out);
}